// round 10
// baseline (speedup 1.0000x reference)
#include <cuda_runtime.h>
#include <cuda_bf16.h>
#include <math.h>
#include <stdint.h>

#define RESO 128
#define NS 8
#define MPTS 65536
#define ZD 64
#define TD 32

typedef __nv_bfloat16 bf16;
typedef __nv_bfloat162 bf162;

// ---------------- helpers ---------------------------------------------------
__device__ __forceinline__ void mma_bf16(float* c, uint32_t a0, uint32_t a1,
                                         uint32_t a2, uint32_t a3,
                                         uint32_t b0, uint32_t b1) {
    asm volatile(
        "mma.sync.aligned.m16n8k16.row.col.f32.bf16.bf16.f32 "
        "{%0,%1,%2,%3}, {%4,%5,%6,%7}, {%8,%9}, {%0,%1,%2,%3};"
        : "+f"(c[0]), "+f"(c[1]), "+f"(c[2]), "+f"(c[3])
        : "r"(a0), "r"(a1), "r"(a2), "r"(a3), "r"(b0), "r"(b1));
}
__device__ __forceinline__ uint32_t packbf(float a, float b) {
    bf162 h = __float22bfloat162_rn(make_float2(a, b));
    return *reinterpret_cast<uint32_t*>(&h);
}

// ---------------- scratch (device globals) ---------------------------------
__device__ bf16 g_fmap_h[NS * RESO * RESO * ZD];            // conv2 out, ch-last
__device__ bf16 g_tri_h[(size_t)NS * 3 * RESO * RESO * TD]; // triplane, ch-last
__device__ float g_zb[NS * ZD];
__device__ float g_A[ZD];
__device__ float g_B[ZD];
__device__ float g_Wz[NS * ZD * 9];
__device__ float g_Wa[ZD * 9];
__device__ float g_Wb[ZD * 9];
__device__ float g_K0[NS * ZD];
__device__ float g_K1[ZD];
__device__ float g_K2[ZD];
__device__ bf16 g_wf2h[9 * 4 * 8 * 128];    // conv2 w frag
__device__ bf16 g_wf3h[9 * 4 * 12 * 128];   // conv3 w frag

// ---------------- merged prep ----------------------------------------------
// block 0: prep (z/A/B) + prep2 (conv1 analytic coeffs)
// blocks 1..160: weight -> bf16 fragment conversion
__global__ void prep_all_kernel(const float* __restrict__ zs, const float* __restrict__ sp,
                                const float* __restrict__ pw, const float* __restrict__ pb,
                                const float* __restrict__ pew, const float* __restrict__ peb,
                                const float* __restrict__ w1, const float* __restrict__ b1,
                                const float* __restrict__ c2w, const float* __restrict__ c3w) {
    int tid = threadIdx.x;
    if (blockIdx.x == 0) {
        if (tid < ZD) {
            int c = tid;
            g_A[c] = pew[0 * ZD + c] - pew[2 * ZD + c];
            g_B[c] = pew[1 * ZD + c] - pew[3 * ZD + c];
            for (int n = 0; n < NS; n++) {
                g_zb[n * ZD + c] = zs[n * ZD + c]
                    + sp[n * 3 + 0] * pw[0 * ZD + c]
                    + sp[n * 3 + 1] * pw[1 * ZD + c]
                    + pb[c] + peb[c];
            }
        }
        __syncthreads();
        const float s = 2.0f / RESO;
        if (tid < ZD * 9) {
            int oc = tid / 9, t = tid % 9;
            float wa = 0.f, wb = 0.f;
            float wz[NS];
#pragma unroll
            for (int n = 0; n < NS; n++) wz[n] = 0.f;
            for (int ic = 0; ic < ZD; ic++) {
                float w = w1[((size_t)oc * ZD + ic) * 9 + t];
                wa += w * g_A[ic];
                wb += w * g_B[ic];
#pragma unroll
                for (int n = 0; n < NS; n++) wz[n] += w * g_zb[n * ZD + ic];
            }
            g_Wa[oc * 9 + t] = wa;
            g_Wb[oc * 9 + t] = wb;
            for (int n = 0; n < NS; n++) g_Wz[(n * ZD + oc) * 9 + t] = wz[n];
        }
        __syncthreads();
        if (tid < ZD) {
            int oc = tid;
            float k1 = 0.f, k2 = 0.f;
            float k0[NS];
            for (int n = 0; n < NS; n++) k0[n] = b1[oc];
            for (int t = 0; t < 9; t++) {
                float dx = (float)(t % 3 - 1), dy = (float)(t / 3 - 1);
                float wa = g_Wa[oc * 9 + t], wb = g_Wb[oc * 9 + t];
                k1 += wa;
                k2 += wb;
                for (int n = 0; n < NS; n++)
                    k0[n] += g_Wz[(n * ZD + oc) * 9 + t] + s * dx * wa + s * dy * wb;
            }
            g_K1[oc] = k1;
            g_K2[oc] = k2;
            for (int n = 0; n < NS; n++) g_K0[n * ZD + oc] = k0[n];
        }
    } else {
        int idx = (blockIdx.x - 1) * 576 + tid;
        if (idx < 9 * 64 * 64) {
            int t = idx / 4096, r2 = idx % 4096;
            int k = r2 / 64, n = r2 % 64;
            int kb = k >> 4, rr = (k >> 3) & 1, half = k & 1;
            int lane = (n & 7) * 4 + ((k & 7) >> 1), nt = n >> 3;
            int word = (t * 32 + kb * 8 + nt) * 64 + lane * 2 + rr;
            g_wf2h[word * 2 + half] = __float2bfloat16(c2w[(size_t)n * 576 + k * 9 + t]);
        } else if (idx < 9 * 64 * 64 + 9 * 64 * 96) {
            int j = idx - 9 * 64 * 64;
            int t = j / 6144, r2 = j % 6144;
            int k = r2 / 96, n = r2 % 96;
            int kb = k >> 4, rr = (k >> 3) & 1, half = k & 1;
            int lane = (n & 7) * 4 + ((k & 7) >> 1), nt = n >> 3;
            int word = (t * 48 + kb * 12 + nt) * 64 + lane * 2 + rr;
            g_wf3h[word * 2 + half] = __float2bfloat16(c3w[(size_t)n * 576 + k * 9 + t]);
        }
    }
}

// ---------------- bf16 tensor-core implicit-GEMM 3x3 conv ------------------
#define X2 72
#define Y2 (34 * X2)
#define SIN_H (6 * Y2)   // bf16 elements

template <int NOC, bool FUSED, bool TRI>
__global__ __launch_bounds__(128, 3) void conv_tc_kernel(
    const uint2* __restrict__ wf, const float* __restrict__ bias,
    const float* __restrict__ c1b, bf16* __restrict__ outh) {
    constexpr int NT = NOC / 8;
    extern __shared__ char shraw[];
    bf16* s_in = (bf16*)shraw;
    float* s_bias = (float*)(shraw + SIN_H * 2);

    const int tid = threadIdx.x;
    const int w = tid >> 5, lane = tid & 31;
    const int x0 = blockIdx.x * 32, y0 = blockIdx.y * 4;
    const int n = blockIdx.z;

    if (tid < NOC) s_bias[tid] = bias[tid];

    const float sgrid = 2.0f / RESO;
    if (FUSED) {
        for (int idx = tid; idx < 6 * 34 * 16; idx += 128) {
            int yi = idx / (34 * 16);
            int rem = idx % (34 * 16);
            int xi = rem / 16, icq = rem % 16;
            int ic4 = icq * 4;
            int gy = y0 + yi - 1, gx = x0 + xi - 1;
            float4 v = make_float4(0.f, 0.f, 0.f, 0.f);
            if (gy >= 0 && gy < RESO && gx >= 0 && gx < RESO) {
                float X = (2 * gx - 127) * (1.0f / RESO);
                float Y = (2 * gy - 127) * (1.0f / RESO);
                if (gx >= 1 && gx <= 126 && gy >= 1 && gy <= 126) {
                    float4 k0 = *(const float4*)&g_K0[n * ZD + ic4];
                    float4 k1 = *(const float4*)&g_K1[ic4];
                    float4 k2 = *(const float4*)&g_K2[ic4];
                    v.x = fmaxf(k0.x + k1.x * X + k2.x * Y, 0.f);
                    v.y = fmaxf(k0.y + k1.y * X + k2.y * Y, 0.f);
                    v.z = fmaxf(k0.z + k1.z * X + k2.z * Y, 0.f);
                    v.w = fmaxf(k0.w + k1.w * X + k2.w * Y, 0.f);
                } else {
                    float vv[4];
#pragma unroll
                    for (int c = 0; c < 4; c++) {
                        int ic = ic4 + c;
                        float val = c1b[ic];
#pragma unroll
                        for (int t9 = 0; t9 < 9; t9++) {
                            int dyb = t9 / 3 - 1, dxb = t9 % 3 - 1;
                            int gy2 = gy + dyb, gx2 = gx + dxb;
                            if (gy2 >= 0 && gy2 < RESO && gx2 >= 0 && gx2 < RESO)
                                val += g_Wz[((size_t)n * ZD + ic) * 9 + t9]
                                     + g_Wa[ic * 9 + t9] * (X + dxb * sgrid)
                                     + g_Wb[ic * 9 + t9] * (Y + dyb * sgrid);
                        }
                        vv[c] = fmaxf(val, 0.f);
                    }
                    v = make_float4(vv[0], vv[1], vv[2], vv[3]);
                }
            }
            uint2 pk;
            pk.x = packbf(v.x, v.y);
            pk.y = packbf(v.z, v.w);
            *(uint2*)&s_in[yi * Y2 + xi * X2 + ic4] = pk;
        }
    } else {
        for (int idx = tid; idx < 6 * 34 * 8; idx += 128) {
            int yi = idx / (34 * 8);
            int rem = idx % (34 * 8);
            int xi = rem / 8, ic8 = (rem % 8) * 8;
            int gy = y0 + yi - 1, gx = x0 + xi - 1;
            uint4 v = make_uint4(0u, 0u, 0u, 0u);
            if (gy >= 0 && gy < RESO && gx >= 0 && gx < RESO)
                v = *(const uint4*)&g_fmap_h[(((size_t)n * RESO + gy) * RESO + gx) * ZD + ic8];
            *(uint4*)&s_in[yi * Y2 + xi * X2 + ic8] = v;
        }
    }
    __syncthreads();   // the ONLY block barrier

    float acc[2][NT][4];
#pragma unroll
    for (int mt = 0; mt < 2; mt++)
#pragma unroll
        for (int nt = 0; nt < NT; nt++)
#pragma unroll
            for (int j = 0; j < 4; j++) acc[mt][nt][j] = 0.f;

    const int q = lane & 3, hr = lane >> 2;

#pragma unroll 1
    for (int tt = 0; tt < 9; tt++) {
        int dy = tt / 3, dx = tt % 3;
#pragma unroll
        for (int kb = 0; kb < 4; kb++) {
            uint2 bb[NT];
#pragma unroll
            for (int nt = 0; nt < NT; nt++)
                bb[nt] = __ldg(&wf[((tt * 4 + kb) * NT + nt) * 32 + lane]);
#pragma unroll
            for (int mt = 0; mt < 2; mt++) {
                const bf16* ap = s_in + (w + dy) * Y2 + (mt * 16 + hr + dx) * X2 + kb * 16;
                uint32_t a0 = *(const uint32_t*)&ap[2 * q];
                uint32_t a1 = *(const uint32_t*)&ap[8 * X2 + 2 * q];
                uint32_t a2 = *(const uint32_t*)&ap[2 * q + 8];
                uint32_t a3 = *(const uint32_t*)&ap[8 * X2 + 2 * q + 8];
#pragma unroll
                for (int nt = 0; nt < NT; nt++)
                    mma_bf16(acc[mt][nt], a0, a1, a2, a3, bb[nt].x, bb[nt].y);
            }
        }
    }

    // ---- epilogue ----
    const int y = y0 + w;
#pragma unroll
    for (int mt = 0; mt < 2; mt++) {
        int xa = x0 + mt * 16 + hr;
#pragma unroll
        for (int nt = 0; nt < NT; nt++) {
            int col = nt * 8 + 2 * q;
            float bv0 = s_bias[col], bv1 = s_bias[col + 1];
            float v0 = acc[mt][nt][0] + bv0, v1 = acc[mt][nt][1] + bv1;
            float v2 = acc[mt][nt][2] + bv0, v3 = acc[mt][nt][3] + bv1;
            if (!TRI) {
                v0 = fmaxf(v0, 0.f); v1 = fmaxf(v1, 0.f);
                v2 = fmaxf(v2, 0.f); v3 = fmaxf(v3, 0.f);
                *(uint32_t*)&outh[(((size_t)n * RESO + y) * RESO + xa) * ZD + col] = packbf(v0, v1);
                *(uint32_t*)&outh[(((size_t)n * RESO + y) * RESO + xa + 8) * ZD + col] = packbf(v2, v3);
            } else {
                int plane = col >> 5, c = col & 31;
                size_t pb = (((size_t)n * 3 + plane) * RESO * RESO);
                *(uint32_t*)&outh[(pb + (size_t)y * RESO + xa) * TD + c] = packbf(v0, v1);
                *(uint32_t*)&outh[(pb + (size_t)y * RESO + xa + 8) * TD + c] = packbf(v2, v3);
            }
        }
    }
}

// ---------------- bf16 decoder + fused composition -------------------------
#define AST2 104
#define D_SA    0
#define D_B0    53248
#define D_B1    71680
#define D_B2    90112
#define D_BI0   96256
#define D_BI1   96640
#define D_BI2   97024
#define D_CW1   97152
#define D_CB1   97440
#define D_UM    97456
#define DEC_SMEM (97456 + 8192)
#define DTILES (MPTS / 32)

template <int NT, bool RELU>
__device__ __forceinline__ void mlp_layer(bf16* sA, const uint32_t* sB,
                                          const float* sbias, int rowbase, int lane) {
    const int g = lane >> 2, q = lane & 3;
    const int cl = 2 * q;
    float acc[2][NT][4];
#pragma unroll
    for (int nt = 0; nt < NT; nt++) {
        float bv0 = sbias[nt * 8 + cl], bv1 = sbias[nt * 8 + cl + 1];
#pragma unroll
        for (int mt = 0; mt < 2; mt++) {
            acc[mt][nt][0] = bv0; acc[mt][nt][1] = bv1;
            acc[mt][nt][2] = bv0; acc[mt][nt][3] = bv1;
        }
    }
#pragma unroll
    for (int kb = 0; kb < 6; kb++) {
        uint2 bb[NT];
#pragma unroll
        for (int nt = 0; nt < NT; nt++)
            bb[nt] = *(const uint2*)&sB[(kb * NT + nt) * 64 + lane * 2];
#pragma unroll
        for (int mt = 0; mt < 2; mt++) {
            const bf16* ap = sA + (rowbase + mt * 16 + g) * AST2 + kb * 16;
            uint32_t a0 = *(const uint32_t*)&ap[2 * q];
            uint32_t a1 = *(const uint32_t*)&ap[8 * AST2 + 2 * q];
            uint32_t a2 = *(const uint32_t*)&ap[2 * q + 8];
            uint32_t a3 = *(const uint32_t*)&ap[8 * AST2 + 2 * q + 8];
#pragma unroll
            for (int nt = 0; nt < NT; nt++)
                mma_bf16(acc[mt][nt], a0, a1, a2, a3, bb[nt].x, bb[nt].y);
        }
    }
#pragma unroll
    for (int mt = 0; mt < 2; mt++) {
        int r0 = rowbase + mt * 16 + g;
#pragma unroll
        for (int nt = 0; nt < NT; nt++) {
            int col = nt * 8 + cl;
            float a0 = acc[mt][nt][0], a1 = acc[mt][nt][1];
            float a2 = acc[mt][nt][2], a3 = acc[mt][nt][3];
            if (RELU) {
                a0 = fmaxf(a0, 0.f); a1 = fmaxf(a1, 0.f);
                a2 = fmaxf(a2, 0.f); a3 = fmaxf(a3, 0.f);
            }
            *(uint32_t*)&sA[r0 * AST2 + col] = packbf(a0, a1);
            *(uint32_t*)&sA[(r0 + 8) * AST2 + col] = packbf(a2, a3);
        }
    }
}

// branch-free clamped bilinear gather of all 3 planes into own sA row
__device__ __forceinline__ void gather_point(bf16* sA, int myrow, int n,
                                             float rx, float ry, float rz) {
#pragma unroll
    for (int p = 0; p < 3; p++) {
        float cu, cv;
        if (p == 0) { cu = rx; cv = ry; }
        else if (p == 1) { cu = rx; cv = rz; }
        else { cu = rz; cv = rx; }
        float u = (cu + 1.f) * 64.f - 0.5f;
        float v = (cv + 1.f) * 64.f - 0.5f;
        float fx = floorf(u), fy = floorf(v);
        float wx = u - fx, wy = v - fy;
        int ix = (int)fx, iy = (int)fy;
        float vx0 = (ix >= 0 && ix <= 127) ? 1.f : 0.f;
        float vx1 = (ix >= -1 && ix <= 126) ? 1.f : 0.f;
        float vy0 = (iy >= 0 && iy <= 127) ? 1.f : 0.f;
        float vy1 = (iy >= -1 && iy <= 126) ? 1.f : 0.f;
        int x0c = min(max(ix, 0), 127), x1c = min(max(ix + 1, 0), 127);
        int y0c = min(max(iy, 0), 127), y1c = min(max(iy + 1, 0), 127);
        bf162 w00 = __float2bfloat162_rn((1.f - wx) * (1.f - wy) * vx0 * vy0);
        bf162 w01 = __float2bfloat162_rn(wx * (1.f - wy) * vx1 * vy0);
        bf162 w10 = __float2bfloat162_rn((1.f - wx) * wy * vx0 * vy1);
        bf162 w11 = __float2bfloat162_rn(wx * wy * vx1 * vy1);
        size_t pb = ((size_t)n * 3 + p) * RESO * RESO;
        const uint4* r00 = (const uint4*)&g_tri_h[(pb + (size_t)y0c * RESO + x0c) * TD];
        const uint4* r01 = (const uint4*)&g_tri_h[(pb + (size_t)y0c * RESO + x1c) * TD];
        const uint4* r10 = (const uint4*)&g_tri_h[(pb + (size_t)y1c * RESO + x0c) * TD];
        const uint4* r11 = (const uint4*)&g_tri_h[(pb + (size_t)y1c * RESO + x1c) * TD];
        bf162 hacc[16];
        {
            uint4 a[4], b[4];
#pragma unroll
            for (int j = 0; j < 4; j++) { a[j] = __ldg(&r00[j]); b[j] = __ldg(&r01[j]); }
#pragma unroll
            for (int j = 0; j < 4; j++) {
                hacc[j * 4 + 0] = __hmul2(*(bf162*)&a[j].x, w00);
                hacc[j * 4 + 1] = __hmul2(*(bf162*)&a[j].y, w00);
                hacc[j * 4 + 2] = __hmul2(*(bf162*)&a[j].z, w00);
                hacc[j * 4 + 3] = __hmul2(*(bf162*)&a[j].w, w00);
                hacc[j * 4 + 0] = __hfma2(*(bf162*)&b[j].x, w01, hacc[j * 4 + 0]);
                hacc[j * 4 + 1] = __hfma2(*(bf162*)&b[j].y, w01, hacc[j * 4 + 1]);
                hacc[j * 4 + 2] = __hfma2(*(bf162*)&b[j].z, w01, hacc[j * 4 + 2]);
                hacc[j * 4 + 3] = __hfma2(*(bf162*)&b[j].w, w01, hacc[j * 4 + 3]);
            }
        }
        {
            uint4 a[4], b[4];
#pragma unroll
            for (int j = 0; j < 4; j++) { a[j] = __ldg(&r10[j]); b[j] = __ldg(&r11[j]); }
#pragma unroll
            for (int j = 0; j < 4; j++) {
                hacc[j * 4 + 0] = __hfma2(*(bf162*)&a[j].x, w10, hacc[j * 4 + 0]);
                hacc[j * 4 + 1] = __hfma2(*(bf162*)&a[j].y, w10, hacc[j * 4 + 1]);
                hacc[j * 4 + 2] = __hfma2(*(bf162*)&a[j].z, w10, hacc[j * 4 + 2]);
                hacc[j * 4 + 3] = __hfma2(*(bf162*)&a[j].w, w10, hacc[j * 4 + 3]);
                hacc[j * 4 + 0] = __hfma2(*(bf162*)&b[j].x, w11, hacc[j * 4 + 0]);
                hacc[j * 4 + 1] = __hfma2(*(bf162*)&b[j].y, w11, hacc[j * 4 + 1]);
                hacc[j * 4 + 2] = __hfma2(*(bf162*)&b[j].z, w11, hacc[j * 4 + 2]);
                hacc[j * 4 + 3] = __hfma2(*(bf162*)&b[j].w, w11, hacc[j * 4 + 3]);
            }
        }
        uint4* dst = (uint4*)&sA[myrow * AST2 + p * 32];
#pragma unroll
        for (int j = 0; j < 4; j++) {
            uint4 o;
            o.x = *(uint32_t*)&hacc[j * 4 + 0];
            o.y = *(uint32_t*)&hacc[j * 4 + 1];
            o.z = *(uint32_t*)&hacc[j * 4 + 2];
            o.w = *(uint32_t*)&hacc[j * 4 + 3];
            dst[j] = o;
        }
    }
}

__global__ __launch_bounds__(256, 2) void decode_kernel(
    const float* __restrict__ coor, const float* __restrict__ spos,
    const float* __restrict__ w0, const float* __restrict__ b0,
    const float* __restrict__ w1, const float* __restrict__ b1,
    const float* __restrict__ dw, const float* __restrict__ db,
    const float* __restrict__ cw0, const float* __restrict__ cb0,
    const float* __restrict__ cw1, const float* __restrict__ cb1,
    float* __restrict__ out) {
    extern __shared__ char smraw[];
    bf16* sA = (bf16*)(smraw + D_SA);
    uint32_t* sB0 = (uint32_t*)(smraw + D_B0);
    uint32_t* sB1 = (uint32_t*)(smraw + D_B1);
    uint32_t* sB2 = (uint32_t*)(smraw + D_B2);
    float* sbi0 = (float*)(smraw + D_BI0);
    float* sbi1 = (float*)(smraw + D_BI1);
    float* sbi2 = (float*)(smraw + D_BI2);
    float* scw1 = (float*)(smraw + D_CW1);
    float* scb1 = (float*)(smraw + D_CB1);
    float4* s_um = (float4*)(smraw + D_UM);   // double-buffered 2x256

    int tid = threadIdx.x;
    int wid = tid >> 5, lane = tid & 31;

    for (int idx = tid; idx < 96 * 96; idx += 256) {
        int k = idx / 96, n = idx % 96;
        int kb = k >> 4, rr = (k >> 3) & 1, half = k & 1;
        int lane2 = (n & 7) * 4 + ((k & 7) >> 1), nt = n >> 3;
        int hoff = ((kb * 12 + nt) * 64 + lane2 * 2 + rr) * 2 + half;
        ((bf16*)sB0)[hoff] = __float2bfloat16(w0[idx]);
        ((bf16*)sB1)[hoff] = __float2bfloat16(w1[idx]);
    }
    for (int idx = tid; idx < 96 * 32; idx += 256) {
        int k = idx / 32, n = idx % 32;
        float v = (n == 0) ? dw[k] : ((n <= 24) ? cw0[k * 24 + n - 1] : 0.f);
        int kb = k >> 4, rr = (k >> 3) & 1, half = k & 1;
        int lane2 = (n & 7) * 4 + ((k & 7) >> 1), nt = n >> 3;
        int hoff = ((kb * 4 + nt) * 64 + lane2 * 2 + rr) * 2 + half;
        ((bf16*)sB2)[hoff] = __float2bfloat16(v);
    }
    if (tid < 96) { sbi0[tid] = b0[tid]; sbi1[tid] = b1[tid]; }
    if (tid < 32) sbi2[tid] = (tid == 0) ? db[0] : ((tid <= 24) ? cb0[tid - 1] : 0.f);
    if (tid < 72) scw1[tid] = cw1[tid];
    if (tid < 3) scb1[tid] = cb1[tid];
    __syncthreads();

    const int rowbase = wid * 32;
    const int myrow = rowbase + lane;
    const int n = wid;   // slot owned by this warp
    const size_t B1o = (size_t)MPTS * 4;
    const size_t B2o = B1o + (size_t)NS * MPTS * 4;
    const size_t B3o = B2o + (size_t)NS * MPTS * 4;
    float sx = spos[n * 3 + 0], sy = spos[n * 3 + 1], sz = spos[n * 3 + 2];
    const int STRIDE = gridDim.x;

    int t0 = blockIdx.x;
    if (t0 < DTILES) {
        // prologue gather
        {
            int m = (t0 << 5) + lane;
            float rx = coor[((size_t)n * MPTS + m) * 3 + 0] - sx;
            float ry = coor[((size_t)n * MPTS + m) * 3 + 1] - sy;
            float rz = coor[((size_t)n * MPTS + m) * 3 + 2] - sz;
            gather_point(sA, myrow, n, rx, ry, rz);
        }
        int buf = 0;
        for (int t = t0; t < DTILES; t += STRIDE, buf ^= 1) {
            int m = (t << 5) + lane;
            float rx = coor[((size_t)n * MPTS + m) * 3 + 0] - sx;
            float ry = coor[((size_t)n * MPTS + m) * 3 + 1] - sy;
            float rz = coor[((size_t)n * MPTS + m) * 3 + 2] - sz;
            bool outsider = (fabsf(rx) > 1.f || fabsf(ry) > 1.f || fabsf(rz) > 1.f);

            __syncwarp();   // gather writes (cross-lane rows) -> mlp reads
            mlp_layer<12, true>(sA, sB0, sbi0, rowbase, lane);
            __syncwarp();
            mlp_layer<12, true>(sA, sB1, sbi1, rowbase, lane);
            __syncwarp();
            mlp_layer<4, false>(sA, sB2, sbi2, rowbase, lane);
            __syncwarp();

            // unmasked raw for own (slot, point)
            float4 um;
            {
                const bf16* vh = &sA[myrow * AST2];
                float vv[26];
#pragma unroll
                for (int i = 0; i < 13; i++) {
                    float2 f2 = __bfloat1622float2(*(const bf162*)&vh[2 * i]);
                    vv[2 * i] = f2.x;
                    vv[2 * i + 1] = f2.y;
                }
                float dens = vv[0];
                float c0 = scb1[0], c1 = scb1[1], c2 = scb1[2];
#pragma unroll
                for (int j = 0; j < 24; j++) {
                    float h = fmaxf(vv[1 + j], 0.f);
                    c0 += h * scw1[j * 3 + 0];
                    c1 += h * scw1[j * 3 + 1];
                    c2 += h * scw1[j * 3 + 2];
                }
                float rawmask = outsider ? 0.f : fmaxf(dens, 0.f);
                um = make_float4((tanhf(c0) + 1.f) * 0.5f, (tanhf(c1) + 1.f) * 0.5f,
                                 (tanhf(c2) + 1.f) * 0.5f, rawmask);
            }
            s_um[buf * 256 + myrow] = um;

            // prefetch next tile's gather (own row only) before the barrier
            int t2 = t + STRIDE;
            if (t2 < DTILES) {
                int m2 = (t2 << 5) + lane;
                float rx2 = coor[((size_t)n * MPTS + m2) * 3 + 0] - sx;
                float ry2 = coor[((size_t)n * MPTS + m2) * 3 + 1] - sy;
                float rz2 = coor[((size_t)n * MPTS + m2) * 3 + 2] - sz;
                gather_point(sA, myrow, n, rx2, ry2, rz2);
            }
            __syncthreads();

            // fused composition
            float denom = 1e-8f;
#pragma unroll
            for (int k = 0; k < NS; k++) denom += s_um[buf * 256 + k * 32 + lane].w;
            float mk = um.w / denom;
            size_t po = (size_t)n * MPTS + m;
            *(float4*)&out[B2o + po * 4] = um;
            *(float4*)&out[B1o + po * 4] = make_float4(um.x * mk, um.y * mk, um.z * mk, um.w * mk);
            out[B3o + po] = mk;
            if (wid == 0) {
                float4 rr = make_float4(0.f, 0.f, 0.f, 0.f);
#pragma unroll
                for (int k = 0; k < NS; k++) {
                    float4 u4 = s_um[buf * 256 + k * 32 + lane];
                    float mkk = u4.w / denom;
                    rr.x += u4.x * mkk; rr.y += u4.y * mkk;
                    rr.z += u4.z * mkk; rr.w += u4.w * mkk;
                }
                *(float4*)&out[(size_t)m * 4] = rr;
            }
        }
    }
}

// ---------------- launch ----------------------------------------------------
extern "C" void kernel_launch(void* const* d_in, const int* in_sizes, int n_in,
                              void* d_out, int out_size) {
    const float* coor = (const float*)d_in[0];
    const float* zs   = (const float*)d_in[1];
    const float* sp   = (const float*)d_in[2];
    const float* pos_w = (const float*)d_in[3];
    const float* pos_b = (const float*)d_in[4];
    const float* pe_w  = (const float*)d_in[5];
    const float* pe_b  = (const float*)d_in[6];
    const float* c1w = (const float*)d_in[7];
    const float* c1b = (const float*)d_in[8];
    const float* c2w = (const float*)d_in[9];
    const float* c2b = (const float*)d_in[10];
    const float* c3w = (const float*)d_in[11];
    const float* c3b = (const float*)d_in[12];
    const float* dw0 = (const float*)d_in[13];
    const float* db0 = (const float*)d_in[14];
    const float* dw1 = (const float*)d_in[15];
    const float* db1 = (const float*)d_in[16];
    const float* dnw = (const float*)d_in[17];
    const float* dnb = (const float*)d_in[18];
    const float* cw0 = (const float*)d_in[19];
    const float* cb0 = (const float*)d_in[20];
    const float* cw1 = (const float*)d_in[21];
    const float* cb1 = (const float*)d_in[22];
    float* out = (float*)d_out;

    bf16 *fmap, *tri, *wf2, *wf3;
    cudaGetSymbolAddress((void**)&fmap, g_fmap_h);
    cudaGetSymbolAddress((void**)&tri, g_tri_h);
    cudaGetSymbolAddress((void**)&wf2, g_wf2h);
    cudaGetSymbolAddress((void**)&wf3, g_wf3h);

    prep_all_kernel<<<161, 576>>>(zs, sp, pos_w, pos_b, pe_w, pe_b,
                                  c1w, c1b, c2w, c3w);

    const int smem2 = SIN_H * 2 + 64 * 4;
    const int smem3 = SIN_H * 2 + 96 * 4;
    cudaFuncSetAttribute((const void*)conv_tc_kernel<64, true, false>,
                         cudaFuncAttributeMaxDynamicSharedMemorySize, smem2);
    cudaFuncSetAttribute((const void*)conv_tc_kernel<96, false, true>,
                         cudaFuncAttributeMaxDynamicSharedMemorySize, smem3);

    dim3 cg(4, 32, NS);
    conv_tc_kernel<64, true, false><<<cg, 128, smem2>>>((const uint2*)wf2, c2b, c1b, fmap);
    conv_tc_kernel<96, false, true><<<cg, 128, smem3>>>((const uint2*)wf3, c3b, c1b, tri);

    cudaFuncSetAttribute(decode_kernel, cudaFuncAttributeMaxDynamicSharedMemorySize, DEC_SMEM);
    decode_kernel<<<296, 256, DEC_SMEM>>>(
        coor, sp, dw0, db0, dw1, db1, dnw, dnb, cw0, cb0, cw1, cb1, out);
}

// round 11
// speedup vs baseline: 1.2553x; 1.2553x over previous
#include <cuda_runtime.h>
#include <cuda_bf16.h>
#include <math.h>
#include <stdint.h>

#define RESO 128
#define NS 8
#define MPTS 65536
#define ZD 64
#define TD 32

typedef __nv_bfloat16 bf16;
typedef __nv_bfloat162 bf162;

// ---------------- helpers ---------------------------------------------------
__device__ __forceinline__ void mma_bf16(float* c, uint32_t a0, uint32_t a1,
                                         uint32_t a2, uint32_t a3,
                                         uint32_t b0, uint32_t b1) {
    asm volatile(
        "mma.sync.aligned.m16n8k16.row.col.f32.bf16.bf16.f32 "
        "{%0,%1,%2,%3}, {%4,%5,%6,%7}, {%8,%9}, {%0,%1,%2,%3};"
        : "+f"(c[0]), "+f"(c[1]), "+f"(c[2]), "+f"(c[3])
        : "r"(a0), "r"(a1), "r"(a2), "r"(a3), "r"(b0), "r"(b1));
}
__device__ __forceinline__ uint32_t packbf(float a, float b) {
    bf162 h = __float22bfloat162_rn(make_float2(a, b));
    return *reinterpret_cast<uint32_t*>(&h);
}

// ---------------- scratch (device globals) ---------------------------------
__device__ bf16 g_fmap_h[NS * RESO * RESO * ZD];            // conv2 out, ch-last
__device__ bf16 g_tri_h[(size_t)NS * 3 * RESO * RESO * TD]; // triplane, ch-last
__device__ float g_zb[NS * ZD];
__device__ float g_A[ZD];
__device__ float g_B[ZD];
__device__ float g_Wz[NS * ZD * 9];
__device__ float g_Wa[ZD * 9];
__device__ float g_Wb[ZD * 9];
__device__ float g_K0[NS * ZD];
__device__ float g_K1[ZD];
__device__ float g_K2[ZD];
__device__ bf16 g_wf2h[9 * 4 * 8 * 128];    // conv2 w frag
__device__ bf16 g_wf3h[9 * 4 * 12 * 128];   // conv3 w frag

// ---------------- merged prep ----------------------------------------------
__global__ void prep_all_kernel(const float* __restrict__ zs, const float* __restrict__ sp,
                                const float* __restrict__ pw, const float* __restrict__ pb,
                                const float* __restrict__ pew, const float* __restrict__ peb,
                                const float* __restrict__ w1, const float* __restrict__ b1,
                                const float* __restrict__ c2w, const float* __restrict__ c3w) {
    int tid = threadIdx.x;
    if (blockIdx.x == 0) {
        if (tid < ZD) {
            int c = tid;
            g_A[c] = pew[0 * ZD + c] - pew[2 * ZD + c];
            g_B[c] = pew[1 * ZD + c] - pew[3 * ZD + c];
            for (int n = 0; n < NS; n++) {
                g_zb[n * ZD + c] = zs[n * ZD + c]
                    + sp[n * 3 + 0] * pw[0 * ZD + c]
                    + sp[n * 3 + 1] * pw[1 * ZD + c]
                    + pb[c] + peb[c];
            }
        }
        __syncthreads();
        const float s = 2.0f / RESO;
        if (tid < ZD * 9) {
            int oc = tid / 9, t = tid % 9;
            float wa = 0.f, wb = 0.f;
            float wz[NS];
#pragma unroll
            for (int n = 0; n < NS; n++) wz[n] = 0.f;
            for (int ic = 0; ic < ZD; ic++) {
                float w = w1[((size_t)oc * ZD + ic) * 9 + t];
                wa += w * g_A[ic];
                wb += w * g_B[ic];
#pragma unroll
                for (int n = 0; n < NS; n++) wz[n] += w * g_zb[n * ZD + ic];
            }
            g_Wa[oc * 9 + t] = wa;
            g_Wb[oc * 9 + t] = wb;
            for (int n = 0; n < NS; n++) g_Wz[(n * ZD + oc) * 9 + t] = wz[n];
        }
        __syncthreads();
        if (tid < ZD) {
            int oc = tid;
            float k1 = 0.f, k2 = 0.f;
            float k0[NS];
            for (int n = 0; n < NS; n++) k0[n] = b1[oc];
            for (int t = 0; t < 9; t++) {
                float dx = (float)(t % 3 - 1), dy = (float)(t / 3 - 1);
                float wa = g_Wa[oc * 9 + t], wb = g_Wb[oc * 9 + t];
                k1 += wa;
                k2 += wb;
                for (int n = 0; n < NS; n++)
                    k0[n] += g_Wz[(n * ZD + oc) * 9 + t] + s * dx * wa + s * dy * wb;
            }
            g_K1[oc] = k1;
            g_K2[oc] = k2;
            for (int n = 0; n < NS; n++) g_K0[n * ZD + oc] = k0[n];
        }
    } else {
        int idx = (blockIdx.x - 1) * 576 + tid;
        if (idx < 9 * 64 * 64) {
            int t = idx / 4096, r2 = idx % 4096;
            int k = r2 / 64, n = r2 % 64;
            int kb = k >> 4, rr = (k >> 3) & 1, half = k & 1;
            int lane = (n & 7) * 4 + ((k & 7) >> 1), nt = n >> 3;
            int word = (t * 32 + kb * 8 + nt) * 64 + lane * 2 + rr;
            g_wf2h[word * 2 + half] = __float2bfloat16(c2w[(size_t)n * 576 + k * 9 + t]);
        } else if (idx < 9 * 64 * 64 + 9 * 64 * 96) {
            int j = idx - 9 * 64 * 64;
            int t = j / 6144, r2 = j % 6144;
            int k = r2 / 96, n = r2 % 96;
            int kb = k >> 4, rr = (k >> 3) & 1, half = k & 1;
            int lane = (n & 7) * 4 + ((k & 7) >> 1), nt = n >> 3;
            int word = (t * 48 + kb * 12 + nt) * 64 + lane * 2 + rr;
            g_wf3h[word * 2 + half] = __float2bfloat16(c3w[(size_t)n * 576 + k * 9 + t]);
        }
    }
}

// ---------------- bf16 tensor-core implicit-GEMM 3x3 conv ------------------
#define X2 72
#define Y2 (34 * X2)
#define SIN_H (6 * Y2)   // bf16 elements

template <int NOC, bool FUSED, bool TRI>
__global__ __launch_bounds__(128, 3) void conv_tc_kernel(
    const uint2* __restrict__ wf, const float* __restrict__ bias,
    const float* __restrict__ c1b, bf16* __restrict__ outh) {
    constexpr int NT = NOC / 8;
    extern __shared__ char shraw[];
    bf16* s_in = (bf16*)shraw;
    float* s_bias = (float*)(shraw + SIN_H * 2);

    const int tid = threadIdx.x;
    const int w = tid >> 5, lane = tid & 31;
    const int x0 = blockIdx.x * 32, y0 = blockIdx.y * 4;
    const int n = blockIdx.z;

    if (tid < NOC) s_bias[tid] = bias[tid];

    const float sgrid = 2.0f / RESO;
    if (FUSED) {
        for (int idx = tid; idx < 6 * 34 * 16; idx += 128) {
            int yi = idx / (34 * 16);
            int rem = idx % (34 * 16);
            int xi = rem / 16, icq = rem % 16;
            int ic4 = icq * 4;
            int gy = y0 + yi - 1, gx = x0 + xi - 1;
            float4 v = make_float4(0.f, 0.f, 0.f, 0.f);
            if (gy >= 0 && gy < RESO && gx >= 0 && gx < RESO) {
                float X = (2 * gx - 127) * (1.0f / RESO);
                float Y = (2 * gy - 127) * (1.0f / RESO);
                if (gx >= 1 && gx <= 126 && gy >= 1 && gy <= 126) {
                    float4 k0 = *(const float4*)&g_K0[n * ZD + ic4];
                    float4 k1 = *(const float4*)&g_K1[ic4];
                    float4 k2 = *(const float4*)&g_K2[ic4];
                    v.x = fmaxf(k0.x + k1.x * X + k2.x * Y, 0.f);
                    v.y = fmaxf(k0.y + k1.y * X + k2.y * Y, 0.f);
                    v.z = fmaxf(k0.z + k1.z * X + k2.z * Y, 0.f);
                    v.w = fmaxf(k0.w + k1.w * X + k2.w * Y, 0.f);
                } else {
                    float vv[4];
#pragma unroll
                    for (int c = 0; c < 4; c++) {
                        int ic = ic4 + c;
                        float val = c1b[ic];
#pragma unroll
                        for (int t9 = 0; t9 < 9; t9++) {
                            int dyb = t9 / 3 - 1, dxb = t9 % 3 - 1;
                            int gy2 = gy + dyb, gx2 = gx + dxb;
                            if (gy2 >= 0 && gy2 < RESO && gx2 >= 0 && gx2 < RESO)
                                val += g_Wz[((size_t)n * ZD + ic) * 9 + t9]
                                     + g_Wa[ic * 9 + t9] * (X + dxb * sgrid)
                                     + g_Wb[ic * 9 + t9] * (Y + dyb * sgrid);
                        }
                        vv[c] = fmaxf(val, 0.f);
                    }
                    v = make_float4(vv[0], vv[1], vv[2], vv[3]);
                }
            }
            uint2 pk;
            pk.x = packbf(v.x, v.y);
            pk.y = packbf(v.z, v.w);
            *(uint2*)&s_in[yi * Y2 + xi * X2 + ic4] = pk;
        }
    } else {
        for (int idx = tid; idx < 6 * 34 * 8; idx += 128) {
            int yi = idx / (34 * 8);
            int rem = idx % (34 * 8);
            int xi = rem / 8, ic8 = (rem % 8) * 8;
            int gy = y0 + yi - 1, gx = x0 + xi - 1;
            uint4 v = make_uint4(0u, 0u, 0u, 0u);
            if (gy >= 0 && gy < RESO && gx >= 0 && gx < RESO)
                v = *(const uint4*)&g_fmap_h[(((size_t)n * RESO + gy) * RESO + gx) * ZD + ic8];
            *(uint4*)&s_in[yi * Y2 + xi * X2 + ic8] = v;
        }
    }
    __syncthreads();

    float acc[2][NT][4];
#pragma unroll
    for (int mt = 0; mt < 2; mt++)
#pragma unroll
        for (int nt = 0; nt < NT; nt++)
#pragma unroll
            for (int j = 0; j < 4; j++) acc[mt][nt][j] = 0.f;

    const int q = lane & 3, hr = lane >> 2;

#pragma unroll 1
    for (int tt = 0; tt < 9; tt++) {
        int dy = tt / 3, dx = tt % 3;
#pragma unroll
        for (int kb = 0; kb < 4; kb++) {
            uint2 bb[NT];
#pragma unroll
            for (int nt = 0; nt < NT; nt++)
                bb[nt] = __ldg(&wf[((tt * 4 + kb) * NT + nt) * 32 + lane]);
#pragma unroll
            for (int mt = 0; mt < 2; mt++) {
                const bf16* ap = s_in + (w + dy) * Y2 + (mt * 16 + hr + dx) * X2 + kb * 16;
                uint32_t a0 = *(const uint32_t*)&ap[2 * q];
                uint32_t a1 = *(const uint32_t*)&ap[8 * X2 + 2 * q];
                uint32_t a2 = *(const uint32_t*)&ap[2 * q + 8];
                uint32_t a3 = *(const uint32_t*)&ap[8 * X2 + 2 * q + 8];
#pragma unroll
                for (int nt = 0; nt < NT; nt++)
                    mma_bf16(acc[mt][nt], a0, a1, a2, a3, bb[nt].x, bb[nt].y);
            }
        }
    }

    const int y = y0 + w;
#pragma unroll
    for (int mt = 0; mt < 2; mt++) {
        int xa = x0 + mt * 16 + hr;
#pragma unroll
        for (int nt = 0; nt < NT; nt++) {
            int col = nt * 8 + 2 * q;
            float bv0 = s_bias[col], bv1 = s_bias[col + 1];
            float v0 = acc[mt][nt][0] + bv0, v1 = acc[mt][nt][1] + bv1;
            float v2 = acc[mt][nt][2] + bv0, v3 = acc[mt][nt][3] + bv1;
            if (!TRI) {
                v0 = fmaxf(v0, 0.f); v1 = fmaxf(v1, 0.f);
                v2 = fmaxf(v2, 0.f); v3 = fmaxf(v3, 0.f);
                *(uint32_t*)&outh[(((size_t)n * RESO + y) * RESO + xa) * ZD + col] = packbf(v0, v1);
                *(uint32_t*)&outh[(((size_t)n * RESO + y) * RESO + xa + 8) * ZD + col] = packbf(v2, v3);
            } else {
                int plane = col >> 5, c = col & 31;
                size_t pb = (((size_t)n * 3 + plane) * RESO * RESO);
                *(uint32_t*)&outh[(pb + (size_t)y * RESO + xa) * TD + c] = packbf(v0, v1);
                *(uint32_t*)&outh[(pb + (size_t)y * RESO + xa + 8) * TD + c] = packbf(v2, v3);
            }
        }
    }
}

// ---------------- bf16 decoder, warp-autonomous, shuffle composition --------
// warp tile: 4 points x 8 slots (lane = point*8 + slot). NO block syncs in loop.
#define AST2 104
#define D_SA    0
#define D_B0    53248
#define D_B1    71680
#define D_B2    90112
#define D_BI0   96256
#define D_BI1   96640
#define D_BI2   97024
#define D_CW1   97152
#define D_CB1   97440
#define DEC_SMEM 97456
#define DTILES (MPTS / 32)

template <int NT, bool RELU>
__device__ __forceinline__ void mlp_layer(bf16* sA, const uint32_t* sB,
                                          const float* sbias, int rowbase, int lane) {
    const int g = lane >> 2, q = lane & 3;
    const int cl = 2 * q;
    float acc[2][NT][4];
#pragma unroll
    for (int nt = 0; nt < NT; nt++) {
        float bv0 = sbias[nt * 8 + cl], bv1 = sbias[nt * 8 + cl + 1];
#pragma unroll
        for (int mt = 0; mt < 2; mt++) {
            acc[mt][nt][0] = bv0; acc[mt][nt][1] = bv1;
            acc[mt][nt][2] = bv0; acc[mt][nt][3] = bv1;
        }
    }
#pragma unroll
    for (int kb = 0; kb < 6; kb++) {
        uint2 bb[NT];
#pragma unroll
        for (int nt = 0; nt < NT; nt++)
            bb[nt] = *(const uint2*)&sB[(kb * NT + nt) * 64 + lane * 2];
#pragma unroll
        for (int mt = 0; mt < 2; mt++) {
            const bf16* ap = sA + (rowbase + mt * 16 + g) * AST2 + kb * 16;
            uint32_t a0 = *(const uint32_t*)&ap[2 * q];
            uint32_t a1 = *(const uint32_t*)&ap[8 * AST2 + 2 * q];
            uint32_t a2 = *(const uint32_t*)&ap[2 * q + 8];
            uint32_t a3 = *(const uint32_t*)&ap[8 * AST2 + 2 * q + 8];
#pragma unroll
            for (int nt = 0; nt < NT; nt++)
                mma_bf16(acc[mt][nt], a0, a1, a2, a3, bb[nt].x, bb[nt].y);
        }
    }
#pragma unroll
    for (int mt = 0; mt < 2; mt++) {
        int r0 = rowbase + mt * 16 + g;
#pragma unroll
        for (int nt = 0; nt < NT; nt++) {
            int col = nt * 8 + cl;
            float a0 = acc[mt][nt][0], a1 = acc[mt][nt][1];
            float a2 = acc[mt][nt][2], a3 = acc[mt][nt][3];
            if (RELU) {
                a0 = fmaxf(a0, 0.f); a1 = fmaxf(a1, 0.f);
                a2 = fmaxf(a2, 0.f); a3 = fmaxf(a3, 0.f);
            }
            *(uint32_t*)&sA[r0 * AST2 + col] = packbf(a0, a1);
            *(uint32_t*)&sA[(r0 + 8) * AST2 + col] = packbf(a2, a3);
        }
    }
}

// round-9 branchy bilinear gather (known-good perf)
__device__ __forceinline__ void gather_point(bf16* sA, int myrow, int n,
                                             float rx, float ry, float rz) {
#pragma unroll
    for (int p = 0; p < 3; p++) {
        float cu, cv;
        if (p == 0) { cu = rx; cv = ry; }
        else if (p == 1) { cu = rx; cv = rz; }
        else { cu = rz; cv = rx; }
        float u = (cu + 1.f) * 64.f - 0.5f;
        float v = (cv + 1.f) * 64.f - 0.5f;
        float fx = floorf(u), fy = floorf(v);
        float wx = u - fx, wy = v - fy;
        int ix0 = (int)fx, iy0 = (int)fy;
        float wts[4] = {(1 - wx) * (1 - wy), wx * (1 - wy), (1 - wx) * wy, wx * wy};
        int xs[4] = {ix0, ix0 + 1, ix0, ix0 + 1};
        int ys[4] = {iy0, iy0, iy0 + 1, iy0 + 1};
        bf162 hacc[16];
#pragma unroll
        for (int k = 0; k < 16; k++) hacc[k] = __float2bfloat162_rn(0.f);
        size_t pb = ((size_t)n * 3 + p) * RESO * RESO;
#pragma unroll
        for (int tt = 0; tt < 4; tt++) {
            if (xs[tt] >= 0 && xs[tt] < RESO && ys[tt] >= 0 && ys[tt] < RESO) {
                const uint4* tq = (const uint4*)&g_tri_h[(pb + (size_t)ys[tt] * RESO + xs[tt]) * TD];
                bf162 w2 = __float2bfloat162_rn(wts[tt]);
#pragma unroll
                for (int j = 0; j < 4; j++) {
                    uint4 qv = tq[j];
                    hacc[j * 4 + 0] = __hfma2(*(bf162*)&qv.x, w2, hacc[j * 4 + 0]);
                    hacc[j * 4 + 1] = __hfma2(*(bf162*)&qv.y, w2, hacc[j * 4 + 1]);
                    hacc[j * 4 + 2] = __hfma2(*(bf162*)&qv.z, w2, hacc[j * 4 + 2]);
                    hacc[j * 4 + 3] = __hfma2(*(bf162*)&qv.w, w2, hacc[j * 4 + 3]);
                }
            }
        }
        uint4* dst = (uint4*)&sA[myrow * AST2 + p * 32];
#pragma unroll
        for (int j = 0; j < 4; j++) {
            uint4 o;
            o.x = *(uint32_t*)&hacc[j * 4 + 0];
            o.y = *(uint32_t*)&hacc[j * 4 + 1];
            o.z = *(uint32_t*)&hacc[j * 4 + 2];
            o.w = *(uint32_t*)&hacc[j * 4 + 3];
            dst[j] = o;
        }
    }
}

__global__ __launch_bounds__(256, 2) void decode_kernel(
    const float* __restrict__ coor, const float* __restrict__ spos,
    const float* __restrict__ w0, const float* __restrict__ b0,
    const float* __restrict__ w1, const float* __restrict__ b1,
    const float* __restrict__ dw, const float* __restrict__ db,
    const float* __restrict__ cw0, const float* __restrict__ cb0,
    const float* __restrict__ cw1, const float* __restrict__ cb1,
    float* __restrict__ out) {
    extern __shared__ char smraw[];
    bf16* sA = (bf16*)(smraw + D_SA);
    uint32_t* sB0 = (uint32_t*)(smraw + D_B0);
    uint32_t* sB1 = (uint32_t*)(smraw + D_B1);
    uint32_t* sB2 = (uint32_t*)(smraw + D_B2);
    float* sbi0 = (float*)(smraw + D_BI0);
    float* sbi1 = (float*)(smraw + D_BI1);
    float* sbi2 = (float*)(smraw + D_BI2);
    float* scw1 = (float*)(smraw + D_CW1);
    float* scb1 = (float*)(smraw + D_CB1);

    int tid = threadIdx.x;
    int wid = tid >> 5, lane = tid & 31;

    for (int idx = tid; idx < 96 * 96; idx += 256) {
        int k = idx / 96, n = idx % 96;
        int kb = k >> 4, rr = (k >> 3) & 1, half = k & 1;
        int lane2 = (n & 7) * 4 + ((k & 7) >> 1), nt = n >> 3;
        int hoff = ((kb * 12 + nt) * 64 + lane2 * 2 + rr) * 2 + half;
        ((bf16*)sB0)[hoff] = __float2bfloat16(w0[idx]);
        ((bf16*)sB1)[hoff] = __float2bfloat16(w1[idx]);
    }
    for (int idx = tid; idx < 96 * 32; idx += 256) {
        int k = idx / 32, n = idx % 32;
        float v = (n == 0) ? dw[k] : ((n <= 24) ? cw0[k * 24 + n - 1] : 0.f);
        int kb = k >> 4, rr = (k >> 3) & 1, half = k & 1;
        int lane2 = (n & 7) * 4 + ((k & 7) >> 1), nt = n >> 3;
        int hoff = ((kb * 4 + nt) * 64 + lane2 * 2 + rr) * 2 + half;
        ((bf16*)sB2)[hoff] = __float2bfloat16(v);
    }
    if (tid < 96) { sbi0[tid] = b0[tid]; sbi1[tid] = b1[tid]; }
    if (tid < 32) sbi2[tid] = (tid == 0) ? db[0] : ((tid <= 24) ? cb0[tid - 1] : 0.f);
    if (tid < 72) scw1[tid] = cw1[tid];
    if (tid < 3) scb1[tid] = cb1[tid];
    __syncthreads();

    const int rowbase = wid * 32;
    const int myrow = rowbase + lane;
    const int slot = lane & 7;       // slot for this lane
    const int pj = lane >> 3;        // point 0..3 within warp
    const size_t B1o = (size_t)MPTS * 4;
    const size_t B2o = B1o + (size_t)NS * MPTS * 4;
    const size_t B3o = B2o + (size_t)NS * MPTS * 4;
    float sx = spos[slot * 3 + 0], sy = spos[slot * 3 + 1], sz = spos[slot * 3 + 2];

    for (int t = blockIdx.x; t < DTILES; t += gridDim.x) {
        int m = (t << 5) + wid * 4 + pj;

        float rx = coor[((size_t)slot * MPTS + m) * 3 + 0] - sx;
        float ry = coor[((size_t)slot * MPTS + m) * 3 + 1] - sy;
        float rz = coor[((size_t)slot * MPTS + m) * 3 + 2] - sz;
        bool outsider = (fabsf(rx) > 1.f || fabsf(ry) > 1.f || fabsf(rz) > 1.f);

        gather_point(sA, myrow, slot, rx, ry, rz);
        __syncwarp();

        mlp_layer<12, true>(sA, sB0, sbi0, rowbase, lane);
        __syncwarp();
        mlp_layer<12, true>(sA, sB1, sbi1, rowbase, lane);
        __syncwarp();
        mlp_layer<4, false>(sA, sB2, sbi2, rowbase, lane);
        __syncwarp();

        // unmasked raw for own (slot, point)
        float4 um;
        {
            const bf16* vh = &sA[myrow * AST2];
            float vv[26];
#pragma unroll
            for (int i = 0; i < 13; i++) {
                float2 f2 = __bfloat1622float2(*(const bf162*)&vh[2 * i]);
                vv[2 * i] = f2.x;
                vv[2 * i + 1] = f2.y;
            }
            float dens = vv[0];
            float c0 = scb1[0], c1 = scb1[1], c2 = scb1[2];
#pragma unroll
            for (int j = 0; j < 24; j++) {
                float h = fmaxf(vv[1 + j], 0.f);
                c0 += h * scw1[j * 3 + 0];
                c1 += h * scw1[j * 3 + 1];
                c2 += h * scw1[j * 3 + 2];
            }
            float rawmask = outsider ? 0.f : fmaxf(dens, 0.f);
            um = make_float4((tanhf(c0) + 1.f) * 0.5f, (tanhf(c1) + 1.f) * 0.5f,
                             (tanhf(c2) + 1.f) * 0.5f, rawmask);
        }

        // composition via shuffles within the 8-lane slot group
        float denom = um.w;
        denom += __shfl_xor_sync(0xffffffffu, denom, 1);
        denom += __shfl_xor_sync(0xffffffffu, denom, 2);
        denom += __shfl_xor_sync(0xffffffffu, denom, 4);
        denom += 1e-8f;
        float mk = um.w / denom;
        float4 md = make_float4(um.x * mk, um.y * mk, um.z * mk, um.w * mk);

        size_t po = (size_t)slot * MPTS + m;
        *(float4*)&out[B2o + po * 4] = um;
        *(float4*)&out[B1o + po * 4] = md;
        out[B3o + po] = mk;

        float r0 = md.x, r1 = md.y, r2 = md.z, r3 = md.w;
#pragma unroll
        for (int d = 1; d <= 4; d <<= 1) {
            r0 += __shfl_xor_sync(0xffffffffu, r0, d);
            r1 += __shfl_xor_sync(0xffffffffu, r1, d);
            r2 += __shfl_xor_sync(0xffffffffu, r2, d);
            r3 += __shfl_xor_sync(0xffffffffu, r3, d);
        }
        if (slot == 0)
            *(float4*)&out[(size_t)m * 4] = make_float4(r0, r1, r2, r3);
        __syncwarp();
    }
}

// ---------------- launch ----------------------------------------------------
extern "C" void kernel_launch(void* const* d_in, const int* in_sizes, int n_in,
                              void* d_out, int out_size) {
    const float* coor = (const float*)d_in[0];
    const float* zs   = (const float*)d_in[1];
    const float* sp   = (const float*)d_in[2];
    const float* pos_w = (const float*)d_in[3];
    const float* pos_b = (const float*)d_in[4];
    const float* pe_w  = (const float*)d_in[5];
    const float* pe_b  = (const float*)d_in[6];
    const float* c1w = (const float*)d_in[7];
    const float* c1b = (const float*)d_in[8];
    const float* c2w = (const float*)d_in[9];
    const float* c2b = (const float*)d_in[10];
    const float* c3w = (const float*)d_in[11];
    const float* c3b = (const float*)d_in[12];
    const float* dw0 = (const float*)d_in[13];
    const float* db0 = (const float*)d_in[14];
    const float* dw1 = (const float*)d_in[15];
    const float* db1 = (const float*)d_in[16];
    const float* dnw = (const float*)d_in[17];
    const float* dnb = (const float*)d_in[18];
    const float* cw0 = (const float*)d_in[19];
    const float* cb0 = (const float*)d_in[20];
    const float* cw1 = (const float*)d_in[21];
    const float* cb1 = (const float*)d_in[22];
    float* out = (float*)d_out;

    bf16 *fmap, *tri, *wf2, *wf3;
    cudaGetSymbolAddress((void**)&fmap, g_fmap_h);
    cudaGetSymbolAddress((void**)&tri, g_tri_h);
    cudaGetSymbolAddress((void**)&wf2, g_wf2h);
    cudaGetSymbolAddress((void**)&wf3, g_wf3h);

    prep_all_kernel<<<161, 576>>>(zs, sp, pos_w, pos_b, pe_w, pe_b,
                                  c1w, c1b, c2w, c3w);

    const int smem2 = SIN_H * 2 + 64 * 4;
    const int smem3 = SIN_H * 2 + 96 * 4;
    cudaFuncSetAttribute((const void*)conv_tc_kernel<64, true, false>,
                         cudaFuncAttributeMaxDynamicSharedMemorySize, smem2);
    cudaFuncSetAttribute((const void*)conv_tc_kernel<96, false, true>,
                         cudaFuncAttributeMaxDynamicSharedMemorySize, smem3);

    dim3 cg(4, 32, NS);
    conv_tc_kernel<64, true, false><<<cg, 128, smem2>>>((const uint2*)wf2, c2b, c1b, fmap);
    conv_tc_kernel<96, false, true><<<cg, 128, smem3>>>((const uint2*)wf3, c3b, c1b, tri);

    cudaFuncSetAttribute(decode_kernel, cudaFuncAttributeMaxDynamicSharedMemorySize, DEC_SMEM);
    decode_kernel<<<296, 256, DEC_SMEM>>>(
        coor, sp, dw0, db0, dw1, db1, dnw, dnb, cw0, cb0, cw1, cb1, out);
}

// round 12
// speedup vs baseline: 1.4777x; 1.1771x over previous
#include <cuda_runtime.h>
#include <cuda_bf16.h>
#include <math.h>
#include <stdint.h>

#define RESO 128
#define NS 8
#define MPTS 65536
#define ZD 64
#define TD 32

typedef __nv_bfloat16 bf16;
typedef __nv_bfloat162 bf162;

// ---------------- helpers ---------------------------------------------------
__device__ __forceinline__ void mma_bf16(float* c, uint32_t a0, uint32_t a1,
                                         uint32_t a2, uint32_t a3,
                                         uint32_t b0, uint32_t b1) {
    asm volatile(
        "mma.sync.aligned.m16n8k16.row.col.f32.bf16.bf16.f32 "
        "{%0,%1,%2,%3}, {%4,%5,%6,%7}, {%8,%9}, {%0,%1,%2,%3};"
        : "+f"(c[0]), "+f"(c[1]), "+f"(c[2]), "+f"(c[3])
        : "r"(a0), "r"(a1), "r"(a2), "r"(a3), "r"(b0), "r"(b1));
}
__device__ __forceinline__ uint32_t packbf(float a, float b) {
    bf162 h = __float22bfloat162_rn(make_float2(a, b));
    return *reinterpret_cast<uint32_t*>(&h);
}

// ---------------- scratch (device globals) ---------------------------------
__device__ bf16 g_fmap_h[NS * RESO * RESO * ZD];            // conv2 out, ch-last
__device__ bf16 g_tri_h[(size_t)NS * 3 * RESO * RESO * TD]; // triplane, ch-last
__device__ float g_zb[NS * ZD];
__device__ float g_A[ZD];
__device__ float g_B[ZD];
__device__ float g_Wz[NS * ZD * 9];
__device__ float g_Wa[ZD * 9];
__device__ float g_Wb[ZD * 9];
__device__ float g_K0[NS * ZD];
__device__ float g_K1[ZD];
__device__ float g_K2[ZD];
__device__ bf16 g_wf2h[9 * 4 * 8 * 128];    // conv2 w frag
__device__ bf16 g_wf3h[9 * 4 * 12 * 128];   // conv3 w frag

// ---------------- merged prep ----------------------------------------------
__global__ void prep_all_kernel(const float* __restrict__ zs, const float* __restrict__ sp,
                                const float* __restrict__ pw, const float* __restrict__ pb,
                                const float* __restrict__ pew, const float* __restrict__ peb,
                                const float* __restrict__ w1, const float* __restrict__ b1,
                                const float* __restrict__ c2w, const float* __restrict__ c3w) {
    int tid = threadIdx.x;
    if (blockIdx.x == 0) {
        if (tid < ZD) {
            int c = tid;
            g_A[c] = pew[0 * ZD + c] - pew[2 * ZD + c];
            g_B[c] = pew[1 * ZD + c] - pew[3 * ZD + c];
            for (int n = 0; n < NS; n++) {
                g_zb[n * ZD + c] = zs[n * ZD + c]
                    + sp[n * 3 + 0] * pw[0 * ZD + c]
                    + sp[n * 3 + 1] * pw[1 * ZD + c]
                    + pb[c] + peb[c];
            }
        }
        __syncthreads();
        const float s = 2.0f / RESO;
        if (tid < ZD * 9) {
            int oc = tid / 9, t = tid % 9;
            float wa = 0.f, wb = 0.f;
            float wz[NS];
#pragma unroll
            for (int n = 0; n < NS; n++) wz[n] = 0.f;
            for (int ic = 0; ic < ZD; ic++) {
                float w = w1[((size_t)oc * ZD + ic) * 9 + t];
                wa += w * g_A[ic];
                wb += w * g_B[ic];
#pragma unroll
                for (int n = 0; n < NS; n++) wz[n] += w * g_zb[n * ZD + ic];
            }
            g_Wa[oc * 9 + t] = wa;
            g_Wb[oc * 9 + t] = wb;
            for (int n = 0; n < NS; n++) g_Wz[(n * ZD + oc) * 9 + t] = wz[n];
        }
        __syncthreads();
        if (tid < ZD) {
            int oc = tid;
            float k1 = 0.f, k2 = 0.f;
            float k0[NS];
            for (int n = 0; n < NS; n++) k0[n] = b1[oc];
            for (int t = 0; t < 9; t++) {
                float dx = (float)(t % 3 - 1), dy = (float)(t / 3 - 1);
                float wa = g_Wa[oc * 9 + t], wb = g_Wb[oc * 9 + t];
                k1 += wa;
                k2 += wb;
                for (int n = 0; n < NS; n++)
                    k0[n] += g_Wz[(n * ZD + oc) * 9 + t] + s * dx * wa + s * dy * wb;
            }
            g_K1[oc] = k1;
            g_K2[oc] = k2;
            for (int n = 0; n < NS; n++) g_K0[n * ZD + oc] = k0[n];
        }
    } else {
        int idx = (blockIdx.x - 1) * 576 + tid;
        if (idx < 9 * 64 * 64) {
            int t = idx / 4096, r2 = idx % 4096;
            int k = r2 / 64, n = r2 % 64;
            int kb = k >> 4, rr = (k >> 3) & 1, half = k & 1;
            int lane = (n & 7) * 4 + ((k & 7) >> 1), nt = n >> 3;
            int word = (t * 32 + kb * 8 + nt) * 64 + lane * 2 + rr;
            g_wf2h[word * 2 + half] = __float2bfloat16(c2w[(size_t)n * 576 + k * 9 + t]);
        } else if (idx < 9 * 64 * 64 + 9 * 64 * 96) {
            int j = idx - 9 * 64 * 64;
            int t = j / 6144, r2 = j % 6144;
            int k = r2 / 96, n = r2 % 96;
            int kb = k >> 4, rr = (k >> 3) & 1, half = k & 1;
            int lane = (n & 7) * 4 + ((k & 7) >> 1), nt = n >> 3;
            int word = (t * 48 + kb * 12 + nt) * 64 + lane * 2 + rr;
            g_wf3h[word * 2 + half] = __float2bfloat16(c3w[(size_t)n * 576 + k * 9 + t]);
        }
    }
}

// ---------------- bf16 tensor-core implicit-GEMM 3x3 conv ------------------
#define X2 72
#define Y2 (34 * X2)
#define SIN_H (6 * Y2)   // bf16 elements

template <int NOC, bool FUSED, bool TRI>
__global__ __launch_bounds__(128, 3) void conv_tc_kernel(
    const uint2* __restrict__ wf, const float* __restrict__ bias,
    const float* __restrict__ c1b, bf16* __restrict__ outh) {
    constexpr int NT = NOC / 8;
    extern __shared__ char shraw[];
    bf16* s_in = (bf16*)shraw;
    float* s_bias = (float*)(shraw + SIN_H * 2);

    const int tid = threadIdx.x;
    const int w = tid >> 5, lane = tid & 31;
    const int x0 = blockIdx.x * 32, y0 = blockIdx.y * 4;
    const int n = blockIdx.z;

    if (tid < NOC) s_bias[tid] = bias[tid];

    const float sgrid = 2.0f / RESO;
    if (FUSED) {
        for (int idx = tid; idx < 6 * 34 * 16; idx += 128) {
            int yi = idx / (34 * 16);
            int rem = idx % (34 * 16);
            int xi = rem / 16, icq = rem % 16;
            int ic4 = icq * 4;
            int gy = y0 + yi - 1, gx = x0 + xi - 1;
            float4 v = make_float4(0.f, 0.f, 0.f, 0.f);
            if (gy >= 0 && gy < RESO && gx >= 0 && gx < RESO) {
                float X = (2 * gx - 127) * (1.0f / RESO);
                float Y = (2 * gy - 127) * (1.0f / RESO);
                if (gx >= 1 && gx <= 126 && gy >= 1 && gy <= 126) {
                    float4 k0 = *(const float4*)&g_K0[n * ZD + ic4];
                    float4 k1 = *(const float4*)&g_K1[ic4];
                    float4 k2 = *(const float4*)&g_K2[ic4];
                    v.x = fmaxf(k0.x + k1.x * X + k2.x * Y, 0.f);
                    v.y = fmaxf(k0.y + k1.y * X + k2.y * Y, 0.f);
                    v.z = fmaxf(k0.z + k1.z * X + k2.z * Y, 0.f);
                    v.w = fmaxf(k0.w + k1.w * X + k2.w * Y, 0.f);
                } else {
                    float vv[4];
#pragma unroll
                    for (int c = 0; c < 4; c++) {
                        int ic = ic4 + c;
                        float val = c1b[ic];
#pragma unroll
                        for (int t9 = 0; t9 < 9; t9++) {
                            int dyb = t9 / 3 - 1, dxb = t9 % 3 - 1;
                            int gy2 = gy + dyb, gx2 = gx + dxb;
                            if (gy2 >= 0 && gy2 < RESO && gx2 >= 0 && gx2 < RESO)
                                val += g_Wz[((size_t)n * ZD + ic) * 9 + t9]
                                     + g_Wa[ic * 9 + t9] * (X + dxb * sgrid)
                                     + g_Wb[ic * 9 + t9] * (Y + dyb * sgrid);
                        }
                        vv[c] = fmaxf(val, 0.f);
                    }
                    v = make_float4(vv[0], vv[1], vv[2], vv[3]);
                }
            }
            uint2 pk;
            pk.x = packbf(v.x, v.y);
            pk.y = packbf(v.z, v.w);
            *(uint2*)&s_in[yi * Y2 + xi * X2 + ic4] = pk;
        }
    } else {
        for (int idx = tid; idx < 6 * 34 * 8; idx += 128) {
            int yi = idx / (34 * 8);
            int rem = idx % (34 * 8);
            int xi = rem / 8, ic8 = (rem % 8) * 8;
            int gy = y0 + yi - 1, gx = x0 + xi - 1;
            uint4 v = make_uint4(0u, 0u, 0u, 0u);
            if (gy >= 0 && gy < RESO && gx >= 0 && gx < RESO)
                v = *(const uint4*)&g_fmap_h[(((size_t)n * RESO + gy) * RESO + gx) * ZD + ic8];
            *(uint4*)&s_in[yi * Y2 + xi * X2 + ic8] = v;
        }
    }
    __syncthreads();

    float acc[2][NT][4];
#pragma unroll
    for (int mt = 0; mt < 2; mt++)
#pragma unroll
        for (int nt = 0; nt < NT; nt++)
#pragma unroll
            for (int j = 0; j < 4; j++) acc[mt][nt][j] = 0.f;

    const int q = lane & 3, hr = lane >> 2;

#pragma unroll 1
    for (int tt = 0; tt < 9; tt++) {
        int dy = tt / 3, dx = tt % 3;
#pragma unroll
        for (int kb = 0; kb < 4; kb++) {
            uint2 bb[NT];
#pragma unroll
            for (int nt = 0; nt < NT; nt++)
                bb[nt] = __ldg(&wf[((tt * 4 + kb) * NT + nt) * 32 + lane]);
#pragma unroll
            for (int mt = 0; mt < 2; mt++) {
                const bf16* ap = s_in + (w + dy) * Y2 + (mt * 16 + hr + dx) * X2 + kb * 16;
                uint32_t a0 = *(const uint32_t*)&ap[2 * q];
                uint32_t a1 = *(const uint32_t*)&ap[8 * X2 + 2 * q];
                uint32_t a2 = *(const uint32_t*)&ap[2 * q + 8];
                uint32_t a3 = *(const uint32_t*)&ap[8 * X2 + 2 * q + 8];
#pragma unroll
                for (int nt = 0; nt < NT; nt++)
                    mma_bf16(acc[mt][nt], a0, a1, a2, a3, bb[nt].x, bb[nt].y);
            }
        }
    }

    const int y = y0 + w;
#pragma unroll
    for (int mt = 0; mt < 2; mt++) {
        int xa = x0 + mt * 16 + hr;
#pragma unroll
        for (int nt = 0; nt < NT; nt++) {
            int col = nt * 8 + 2 * q;
            float bv0 = s_bias[col], bv1 = s_bias[col + 1];
            float v0 = acc[mt][nt][0] + bv0, v1 = acc[mt][nt][1] + bv1;
            float v2 = acc[mt][nt][2] + bv0, v3 = acc[mt][nt][3] + bv1;
            if (!TRI) {
                v0 = fmaxf(v0, 0.f); v1 = fmaxf(v1, 0.f);
                v2 = fmaxf(v2, 0.f); v3 = fmaxf(v3, 0.f);
                *(uint32_t*)&outh[(((size_t)n * RESO + y) * RESO + xa) * ZD + col] = packbf(v0, v1);
                *(uint32_t*)&outh[(((size_t)n * RESO + y) * RESO + xa + 8) * ZD + col] = packbf(v2, v3);
            } else {
                int plane = col >> 5, c = col & 31;
                size_t pb = (((size_t)n * 3 + plane) * RESO * RESO);
                *(uint32_t*)&outh[(pb + (size_t)y * RESO + xa) * TD + c] = packbf(v0, v1);
                *(uint32_t*)&outh[(pb + (size_t)y * RESO + xa + 8) * TD + c] = packbf(v2, v3);
            }
        }
    }
}

// ---------------- bf16 decoder, warp-autonomous, shuffle composition --------
// warp tile: 4 points x 8 slots (lane = point*8 + slot). NO block syncs in loop.
#define AST2 104
#define D_SA    0
#define D_B0    53248
#define D_B1    71680
#define D_B2    90112
#define D_BI0   96256
#define D_BI1   96640
#define D_BI2   97024
#define D_CW1   97152
#define D_CB1   97440
#define DEC_SMEM 97456
#define DTILES (MPTS / 32)

template <int NT, bool RELU>
__device__ __forceinline__ void mlp_layer(bf16* sA, const uint32_t* sB,
                                          const float* sbias, int rowbase, int lane) {
    const int g = lane >> 2, q = lane & 3;
    const int cl = 2 * q;
    float acc[2][NT][4];
#pragma unroll
    for (int nt = 0; nt < NT; nt++) {
        float bv0 = sbias[nt * 8 + cl], bv1 = sbias[nt * 8 + cl + 1];
#pragma unroll
        for (int mt = 0; mt < 2; mt++) {
            acc[mt][nt][0] = bv0; acc[mt][nt][1] = bv1;
            acc[mt][nt][2] = bv0; acc[mt][nt][3] = bv1;
        }
    }
#pragma unroll
    for (int kb = 0; kb < 6; kb++) {
        uint2 bb[NT];
#pragma unroll
        for (int nt = 0; nt < NT; nt++)
            bb[nt] = *(const uint2*)&sB[(kb * NT + nt) * 64 + lane * 2];
#pragma unroll
        for (int mt = 0; mt < 2; mt++) {
            const bf16* ap = sA + (rowbase + mt * 16 + g) * AST2 + kb * 16;
            uint32_t a0 = *(const uint32_t*)&ap[2 * q];
            uint32_t a1 = *(const uint32_t*)&ap[8 * AST2 + 2 * q];
            uint32_t a2 = *(const uint32_t*)&ap[2 * q + 8];
            uint32_t a3 = *(const uint32_t*)&ap[8 * AST2 + 2 * q + 8];
#pragma unroll
            for (int nt = 0; nt < NT; nt++)
                mma_bf16(acc[mt][nt], a0, a1, a2, a3, bb[nt].x, bb[nt].y);
        }
    }
#pragma unroll
    for (int mt = 0; mt < 2; mt++) {
        int r0 = rowbase + mt * 16 + g;
#pragma unroll
        for (int nt = 0; nt < NT; nt++) {
            int col = nt * 8 + cl;
            float a0 = acc[mt][nt][0], a1 = acc[mt][nt][1];
            float a2 = acc[mt][nt][2], a3 = acc[mt][nt][3];
            if (RELU) {
                a0 = fmaxf(a0, 0.f); a1 = fmaxf(a1, 0.f);
                a2 = fmaxf(a2, 0.f); a3 = fmaxf(a3, 0.f);
            }
            *(uint32_t*)&sA[r0 * AST2 + col] = packbf(a0, a1);
            *(uint32_t*)&sA[(r0 + 8) * AST2 + col] = packbf(a2, a3);
        }
    }
}

__global__ __launch_bounds__(256, 2) void decode_kernel(
    const float* __restrict__ coor, const float* __restrict__ spos,
    const float* __restrict__ w0, const float* __restrict__ b0,
    const float* __restrict__ w1, const float* __restrict__ b1,
    const float* __restrict__ dw, const float* __restrict__ db,
    const float* __restrict__ cw0, const float* __restrict__ cb0,
    const float* __restrict__ cw1, const float* __restrict__ cb1,
    float* __restrict__ out) {
    extern __shared__ char smraw[];
    bf16* sA = (bf16*)(smraw + D_SA);
    uint32_t* sB0 = (uint32_t*)(smraw + D_B0);
    uint32_t* sB1 = (uint32_t*)(smraw + D_B1);
    uint32_t* sB2 = (uint32_t*)(smraw + D_B2);
    float* sbi0 = (float*)(smraw + D_BI0);
    float* sbi1 = (float*)(smraw + D_BI1);
    float* sbi2 = (float*)(smraw + D_BI2);
    float* scw1 = (float*)(smraw + D_CW1);
    float* scb1 = (float*)(smraw + D_CB1);

    int tid = threadIdx.x;
    int wid = tid >> 5, lane = tid & 31;

    for (int idx = tid; idx < 96 * 96; idx += 256) {
        int k = idx / 96, n = idx % 96;
        int kb = k >> 4, rr = (k >> 3) & 1, half = k & 1;
        int lane2 = (n & 7) * 4 + ((k & 7) >> 1), nt = n >> 3;
        int hoff = ((kb * 12 + nt) * 64 + lane2 * 2 + rr) * 2 + half;
        ((bf16*)sB0)[hoff] = __float2bfloat16(w0[idx]);
        ((bf16*)sB1)[hoff] = __float2bfloat16(w1[idx]);
    }
    for (int idx = tid; idx < 96 * 32; idx += 256) {
        int k = idx / 32, n = idx % 32;
        float v = (n == 0) ? dw[k] : ((n <= 24) ? cw0[k * 24 + n - 1] : 0.f);
        int kb = k >> 4, rr = (k >> 3) & 1, half = k & 1;
        int lane2 = (n & 7) * 4 + ((k & 7) >> 1), nt = n >> 3;
        int hoff = ((kb * 4 + nt) * 64 + lane2 * 2 + rr) * 2 + half;
        ((bf16*)sB2)[hoff] = __float2bfloat16(v);
    }
    if (tid < 96) { sbi0[tid] = b0[tid]; sbi1[tid] = b1[tid]; }
    if (tid < 32) sbi2[tid] = (tid == 0) ? db[0] : ((tid <= 24) ? cb0[tid - 1] : 0.f);
    if (tid < 72) scw1[tid] = cw1[tid];
    if (tid < 3) scb1[tid] = cb1[tid];
    __syncthreads();

    const int rowbase = wid * 32;
    const int myrow = rowbase + lane;
    const int slot = lane & 7;       // slot for this lane's own row
    const int pj = lane >> 3;        // point 0..3 within warp
    const int g2 = lane >> 2;        // gather: row-in-group
    const int ch = (lane & 3) * 8;   // gather: channel chunk (8 bf16)
    const size_t B1o = (size_t)MPTS * 4;
    const size_t B2o = B1o + (size_t)NS * MPTS * 4;
    const size_t B3o = B2o + (size_t)NS * MPTS * 4;
    float sx = spos[slot * 3 + 0], sy = spos[slot * 3 + 1], sz = spos[slot * 3 + 2];

    for (int t = blockIdx.x; t < DTILES; t += gridDim.x) {
        int m = (t << 5) + wid * 4 + pj;

        float rx = coor[((size_t)slot * MPTS + m) * 3 + 0] - sx;
        float ry = coor[((size_t)slot * MPTS + m) * 3 + 1] - sy;
        float rz = coor[((size_t)slot * MPTS + m) * 3 + 2] - sz;
        bool outsider = (fabsf(rx) > 1.f || fabsf(ry) > 1.f || fabsf(rz) > 1.f);

        // own-row per-plane sample coords
        float up0 = (rx + 1.f) * 64.f - 0.5f, vp0 = (ry + 1.f) * 64.f - 0.5f;
        float up1 = up0,                      vp1 = (rz + 1.f) * 64.f - 0.5f;
        float up2 = vp1,                      vp2 = up0;   // plane2: (z, x)

        // cooperative coalesced gather: 4-lane groups load 64B-contiguous texels
#pragma unroll
        for (int p = 0; p < 3; p++) {
            float uo = (p == 0) ? up0 : (p == 1) ? up1 : up2;
            float vo = (p == 0) ? vp0 : (p == 1) ? vp1 : vp2;
#pragma unroll
            for (int it = 0; it < 4; it++) {
                int r = it * 8 + g2;                 // warp-relative row handled
                float u = __shfl_sync(0xffffffffu, uo, r);
                float v = __shfl_sync(0xffffffffu, vo, r);
                float fx = floorf(u), fy = floorf(v);
                float wx = u - fx, wy = v - fy;
                int ix0 = (int)fx, iy0 = (int)fy;
                float wts[4] = {(1 - wx) * (1 - wy), wx * (1 - wy), (1 - wx) * wy, wx * wy};
                int xs[4] = {ix0, ix0 + 1, ix0, ix0 + 1};
                int ys[4] = {iy0, iy0, iy0 + 1, iy0 + 1};
                int rslot = r & 7;
                size_t pb = ((size_t)rslot * 3 + p) * RESO * RESO;
                bf162 acc4[4];
#pragma unroll
                for (int k = 0; k < 4; k++) acc4[k] = __float2bfloat162_rn(0.f);
#pragma unroll
                for (int tt = 0; tt < 4; tt++) {
                    if (xs[tt] >= 0 && xs[tt] < RESO && ys[tt] >= 0 && ys[tt] < RESO) {
                        uint4 qv = __ldg((const uint4*)&g_tri_h[(pb + (size_t)ys[tt] * RESO + xs[tt]) * TD + ch]);
                        bf162 w2 = __float2bfloat162_rn(wts[tt]);
                        acc4[0] = __hfma2(*(bf162*)&qv.x, w2, acc4[0]);
                        acc4[1] = __hfma2(*(bf162*)&qv.y, w2, acc4[1]);
                        acc4[2] = __hfma2(*(bf162*)&qv.z, w2, acc4[2]);
                        acc4[3] = __hfma2(*(bf162*)&qv.w, w2, acc4[3]);
                    }
                }
                uint4 o;
                o.x = *(uint32_t*)&acc4[0];
                o.y = *(uint32_t*)&acc4[1];
                o.z = *(uint32_t*)&acc4[2];
                o.w = *(uint32_t*)&acc4[3];
                *(uint4*)&sA[(rowbase + r) * AST2 + p * 32 + ch] = o;
            }
        }
        __syncwarp();

        mlp_layer<12, true>(sA, sB0, sbi0, rowbase, lane);
        __syncwarp();
        mlp_layer<12, true>(sA, sB1, sbi1, rowbase, lane);
        __syncwarp();
        mlp_layer<4, false>(sA, sB2, sbi2, rowbase, lane);
        __syncwarp();

        // unmasked raw for own (slot, point)
        float4 um;
        {
            const bf16* vh = &sA[myrow * AST2];
            float vv[26];
#pragma unroll
            for (int i = 0; i < 13; i++) {
                float2 f2 = __bfloat1622float2(*(const bf162*)&vh[2 * i]);
                vv[2 * i] = f2.x;
                vv[2 * i + 1] = f2.y;
            }
            float dens = vv[0];
            float c0 = scb1[0], c1 = scb1[1], c2 = scb1[2];
#pragma unroll
            for (int j = 0; j < 24; j++) {
                float h = fmaxf(vv[1 + j], 0.f);
                c0 += h * scw1[j * 3 + 0];
                c1 += h * scw1[j * 3 + 1];
                c2 += h * scw1[j * 3 + 2];
            }
            float rawmask = outsider ? 0.f : fmaxf(dens, 0.f);
            um = make_float4((tanhf(c0) + 1.f) * 0.5f, (tanhf(c1) + 1.f) * 0.5f,
                             (tanhf(c2) + 1.f) * 0.5f, rawmask);
        }

        // composition via shuffles within the 8-lane slot group
        float denom = um.w;
        denom += __shfl_xor_sync(0xffffffffu, denom, 1);
        denom += __shfl_xor_sync(0xffffffffu, denom, 2);
        denom += __shfl_xor_sync(0xffffffffu, denom, 4);
        denom += 1e-8f;
        float mk = um.w / denom;
        float4 md = make_float4(um.x * mk, um.y * mk, um.z * mk, um.w * mk);

        size_t po = (size_t)slot * MPTS + m;
        *(float4*)&out[B2o + po * 4] = um;
        *(float4*)&out[B1o + po * 4] = md;
        out[B3o + po] = mk;

        float r0 = md.x, r1 = md.y, r2 = md.z, r3 = md.w;
#pragma unroll
        for (int d = 1; d <= 4; d <<= 1) {
            r0 += __shfl_xor_sync(0xffffffffu, r0, d);
            r1 += __shfl_xor_sync(0xffffffffu, r1, d);
            r2 += __shfl_xor_sync(0xffffffffu, r2, d);
            r3 += __shfl_xor_sync(0xffffffffu, r3, d);
        }
        if (slot == 0)
            *(float4*)&out[(size_t)m * 4] = make_float4(r0, r1, r2, r3);
        __syncwarp();
    }
}

// ---------------- launch ----------------------------------------------------
extern "C" void kernel_launch(void* const* d_in, const int* in_sizes, int n_in,
                              void* d_out, int out_size) {
    const float* coor = (const float*)d_in[0];
    const float* zs   = (const float*)d_in[1];
    const float* sp   = (const float*)d_in[2];
    const float* pos_w = (const float*)d_in[3];
    const float* pos_b = (const float*)d_in[4];
    const float* pe_w  = (const float*)d_in[5];
    const float* pe_b  = (const float*)d_in[6];
    const float* c1w = (const float*)d_in[7];
    const float* c1b = (const float*)d_in[8];
    const float* c2w = (const float*)d_in[9];
    const float* c2b = (const float*)d_in[10];
    const float* c3w = (const float*)d_in[11];
    const float* c3b = (const float*)d_in[12];
    const float* dw0 = (const float*)d_in[13];
    const float* db0 = (const float*)d_in[14];
    const float* dw1 = (const float*)d_in[15];
    const float* db1 = (const float*)d_in[16];
    const float* dnw = (const float*)d_in[17];
    const float* dnb = (const float*)d_in[18];
    const float* cw0 = (const float*)d_in[19];
    const float* cb0 = (const float*)d_in[20];
    const float* cw1 = (const float*)d_in[21];
    const float* cb1 = (const float*)d_in[22];
    float* out = (float*)d_out;

    bf16 *fmap, *tri, *wf2, *wf3;
    cudaGetSymbolAddress((void**)&fmap, g_fmap_h);
    cudaGetSymbolAddress((void**)&tri, g_tri_h);
    cudaGetSymbolAddress((void**)&wf2, g_wf2h);
    cudaGetSymbolAddress((void**)&wf3, g_wf3h);

    prep_all_kernel<<<161, 576>>>(zs, sp, pos_w, pos_b, pe_w, pe_b,
                                  c1w, c1b, c2w, c3w);

    const int smem2 = SIN_H * 2 + 64 * 4;
    const int smem3 = SIN_H * 2 + 96 * 4;
    cudaFuncSetAttribute((const void*)conv_tc_kernel<64, true, false>,
                         cudaFuncAttributeMaxDynamicSharedMemorySize, smem2);
    cudaFuncSetAttribute((const void*)conv_tc_kernel<96, false, true>,
                         cudaFuncAttributeMaxDynamicSharedMemorySize, smem3);

    dim3 cg(4, 32, NS);
    conv_tc_kernel<64, true, false><<<cg, 128, smem2>>>((const uint2*)wf2, c2b, c1b, fmap);
    conv_tc_kernel<96, false, true><<<cg, 128, smem3>>>((const uint2*)wf3, c3b, c1b, tri);

    cudaFuncSetAttribute(decode_kernel, cudaFuncAttributeMaxDynamicSharedMemorySize, DEC_SMEM);
    decode_kernel<<<296, 256, DEC_SMEM>>>(
        coor, sp, dw0, db0, dw1, db1, dnw, dnb, cw0, cb0, cw1, cb1, out);
}

// round 13
// speedup vs baseline: 1.5575x; 1.0540x over previous
#include <cuda_runtime.h>
#include <cuda_bf16.h>
#include <math.h>
#include <stdint.h>

#define RESO 128
#define NS 8
#define MPTS 65536
#define ZD 64
#define TD 32

typedef __nv_bfloat16 bf16;
typedef __nv_bfloat162 bf162;

// ---------------- helpers ---------------------------------------------------
__device__ __forceinline__ void mma_bf16(float* c, uint32_t a0, uint32_t a1,
                                         uint32_t a2, uint32_t a3,
                                         uint32_t b0, uint32_t b1) {
    asm volatile(
        "mma.sync.aligned.m16n8k16.row.col.f32.bf16.bf16.f32 "
        "{%0,%1,%2,%3}, {%4,%5,%6,%7}, {%8,%9}, {%0,%1,%2,%3};"
        : "+f"(c[0]), "+f"(c[1]), "+f"(c[2]), "+f"(c[3])
        : "r"(a0), "r"(a1), "r"(a2), "r"(a3), "r"(b0), "r"(b1));
}
__device__ __forceinline__ uint32_t packbf(float a, float b) {
    bf162 h = __float22bfloat162_rn(make_float2(a, b));
    return *reinterpret_cast<uint32_t*>(&h);
}

// ---------------- scratch (device globals) ---------------------------------
__device__ bf16 g_fmap_h[NS * RESO * RESO * ZD];            // conv2 out, ch-last
__device__ bf16 g_tri_h[(size_t)NS * 3 * RESO * RESO * TD]; // triplane, ch-last
__device__ float g_zb[NS * ZD];
__device__ float g_A[ZD];
__device__ float g_B[ZD];
__device__ float g_Wz[NS * ZD * 9];
__device__ float g_Wa[ZD * 9];
__device__ float g_Wb[ZD * 9];
__device__ float g_K0[NS * ZD];
__device__ float g_K1[ZD];
__device__ float g_K2[ZD];
__device__ bf16 g_wf2h[9 * 4 * 8 * 128];    // conv2 w frag
__device__ bf16 g_wf3h[9 * 4 * 12 * 128];   // conv3 w frag

// ---------------- merged prep ----------------------------------------------
__global__ void prep_all_kernel(const float* __restrict__ zs, const float* __restrict__ sp,
                                const float* __restrict__ pw, const float* __restrict__ pb,
                                const float* __restrict__ pew, const float* __restrict__ peb,
                                const float* __restrict__ w1, const float* __restrict__ b1,
                                const float* __restrict__ c2w, const float* __restrict__ c3w) {
    int tid = threadIdx.x;
    if (blockIdx.x == 0) {
        if (tid < ZD) {
            int c = tid;
            g_A[c] = pew[0 * ZD + c] - pew[2 * ZD + c];
            g_B[c] = pew[1 * ZD + c] - pew[3 * ZD + c];
            for (int n = 0; n < NS; n++) {
                g_zb[n * ZD + c] = zs[n * ZD + c]
                    + sp[n * 3 + 0] * pw[0 * ZD + c]
                    + sp[n * 3 + 1] * pw[1 * ZD + c]
                    + pb[c] + peb[c];
            }
        }
        __syncthreads();
        const float s = 2.0f / RESO;
        if (tid < ZD * 9) {
            int oc = tid / 9, t = tid % 9;
            float wa = 0.f, wb = 0.f;
            float wz[NS];
#pragma unroll
            for (int n = 0; n < NS; n++) wz[n] = 0.f;
            for (int ic = 0; ic < ZD; ic++) {
                float w = w1[((size_t)oc * ZD + ic) * 9 + t];
                wa += w * g_A[ic];
                wb += w * g_B[ic];
#pragma unroll
                for (int n = 0; n < NS; n++) wz[n] += w * g_zb[n * ZD + ic];
            }
            g_Wa[oc * 9 + t] = wa;
            g_Wb[oc * 9 + t] = wb;
            for (int n = 0; n < NS; n++) g_Wz[(n * ZD + oc) * 9 + t] = wz[n];
        }
        __syncthreads();
        if (tid < ZD) {
            int oc = tid;
            float k1 = 0.f, k2 = 0.f;
            float k0[NS];
            for (int n = 0; n < NS; n++) k0[n] = b1[oc];
            for (int t = 0; t < 9; t++) {
                float dx = (float)(t % 3 - 1), dy = (float)(t / 3 - 1);
                float wa = g_Wa[oc * 9 + t], wb = g_Wb[oc * 9 + t];
                k1 += wa;
                k2 += wb;
                for (int n = 0; n < NS; n++)
                    k0[n] += g_Wz[(n * ZD + oc) * 9 + t] + s * dx * wa + s * dy * wb;
            }
            g_K1[oc] = k1;
            g_K2[oc] = k2;
            for (int n = 0; n < NS; n++) g_K0[n * ZD + oc] = k0[n];
        }
    } else {
        int idx = (blockIdx.x - 1) * 576 + tid;
        if (idx < 9 * 64 * 64) {
            int t = idx / 4096, r2 = idx % 4096;
            int k = r2 / 64, n = r2 % 64;
            int kb = k >> 4, rr = (k >> 3) & 1, half = k & 1;
            int lane = (n & 7) * 4 + ((k & 7) >> 1), nt = n >> 3;
            int word = (t * 32 + kb * 8 + nt) * 64 + lane * 2 + rr;
            g_wf2h[word * 2 + half] = __float2bfloat16(c2w[(size_t)n * 576 + k * 9 + t]);
        } else if (idx < 9 * 64 * 64 + 9 * 64 * 96) {
            int j = idx - 9 * 64 * 64;
            int t = j / 6144, r2 = j % 6144;
            int k = r2 / 96, n = r2 % 96;
            int kb = k >> 4, rr = (k >> 3) & 1, half = k & 1;
            int lane = (n & 7) * 4 + ((k & 7) >> 1), nt = n >> 3;
            int word = (t * 48 + kb * 12 + nt) * 64 + lane * 2 + rr;
            g_wf3h[word * 2 + half] = __float2bfloat16(c3w[(size_t)n * 576 + k * 9 + t]);
        }
    }
}

// ---------------- bf16 tensor-core implicit-GEMM 3x3 conv ------------------
#define X2 72
#define Y2 (34 * X2)
#define SIN_H (6 * Y2)   // bf16 elements

template <int NOC, bool FUSED, bool TRI>
__global__ __launch_bounds__(128, 3) void conv_tc_kernel(
    const uint2* __restrict__ wf, const float* __restrict__ bias,
    const float* __restrict__ c1b, bf16* __restrict__ outh) {
    constexpr int NT = NOC / 8;
    extern __shared__ char shraw[];
    bf16* s_in = (bf16*)shraw;
    float* s_bias = (float*)(shraw + SIN_H * 2);

    const int tid = threadIdx.x;
    const int w = tid >> 5, lane = tid & 31;
    const int x0 = blockIdx.x * 32, y0 = blockIdx.y * 4;
    const int n = blockIdx.z;

    if (tid < NOC) s_bias[tid] = bias[tid];

    const float sgrid = 2.0f / RESO;
    if (FUSED) {
        for (int idx = tid; idx < 6 * 34 * 16; idx += 128) {
            int yi = idx / (34 * 16);
            int rem = idx % (34 * 16);
            int xi = rem / 16, icq = rem % 16;
            int ic4 = icq * 4;
            int gy = y0 + yi - 1, gx = x0 + xi - 1;
            float4 v = make_float4(0.f, 0.f, 0.f, 0.f);
            if (gy >= 0 && gy < RESO && gx >= 0 && gx < RESO) {
                float X = (2 * gx - 127) * (1.0f / RESO);
                float Y = (2 * gy - 127) * (1.0f / RESO);
                if (gx >= 1 && gx <= 126 && gy >= 1 && gy <= 126) {
                    float4 k0 = *(const float4*)&g_K0[n * ZD + ic4];
                    float4 k1 = *(const float4*)&g_K1[ic4];
                    float4 k2 = *(const float4*)&g_K2[ic4];
                    v.x = fmaxf(k0.x + k1.x * X + k2.x * Y, 0.f);
                    v.y = fmaxf(k0.y + k1.y * X + k2.y * Y, 0.f);
                    v.z = fmaxf(k0.z + k1.z * X + k2.z * Y, 0.f);
                    v.w = fmaxf(k0.w + k1.w * X + k2.w * Y, 0.f);
                } else {
                    float vv[4];
#pragma unroll
                    for (int c = 0; c < 4; c++) {
                        int ic = ic4 + c;
                        float val = c1b[ic];
#pragma unroll
                        for (int t9 = 0; t9 < 9; t9++) {
                            int dyb = t9 / 3 - 1, dxb = t9 % 3 - 1;
                            int gy2 = gy + dyb, gx2 = gx + dxb;
                            if (gy2 >= 0 && gy2 < RESO && gx2 >= 0 && gx2 < RESO)
                                val += g_Wz[((size_t)n * ZD + ic) * 9 + t9]
                                     + g_Wa[ic * 9 + t9] * (X + dxb * sgrid)
                                     + g_Wb[ic * 9 + t9] * (Y + dyb * sgrid);
                        }
                        vv[c] = fmaxf(val, 0.f);
                    }
                    v = make_float4(vv[0], vv[1], vv[2], vv[3]);
                }
            }
            uint2 pk;
            pk.x = packbf(v.x, v.y);
            pk.y = packbf(v.z, v.w);
            *(uint2*)&s_in[yi * Y2 + xi * X2 + ic4] = pk;
        }
    } else {
        for (int idx = tid; idx < 6 * 34 * 8; idx += 128) {
            int yi = idx / (34 * 8);
            int rem = idx % (34 * 8);
            int xi = rem / 8, ic8 = (rem % 8) * 8;
            int gy = y0 + yi - 1, gx = x0 + xi - 1;
            uint4 v = make_uint4(0u, 0u, 0u, 0u);
            if (gy >= 0 && gy < RESO && gx >= 0 && gx < RESO)
                v = *(const uint4*)&g_fmap_h[(((size_t)n * RESO + gy) * RESO + gx) * ZD + ic8];
            *(uint4*)&s_in[yi * Y2 + xi * X2 + ic8] = v;
        }
    }
    __syncthreads();

    float acc[2][NT][4];
#pragma unroll
    for (int mt = 0; mt < 2; mt++)
#pragma unroll
        for (int nt = 0; nt < NT; nt++)
#pragma unroll
            for (int j = 0; j < 4; j++) acc[mt][nt][j] = 0.f;

    const int q = lane & 3, hr = lane >> 2;

#pragma unroll 1
    for (int tt = 0; tt < 9; tt++) {
        int dy = tt / 3, dx = tt % 3;
#pragma unroll
        for (int kb = 0; kb < 4; kb++) {
            uint2 bb[NT];
#pragma unroll
            for (int nt = 0; nt < NT; nt++)
                bb[nt] = __ldg(&wf[((tt * 4 + kb) * NT + nt) * 32 + lane]);
#pragma unroll
            for (int mt = 0; mt < 2; mt++) {
                const bf16* ap = s_in + (w + dy) * Y2 + (mt * 16 + hr + dx) * X2 + kb * 16;
                uint32_t a0 = *(const uint32_t*)&ap[2 * q];
                uint32_t a1 = *(const uint32_t*)&ap[8 * X2 + 2 * q];
                uint32_t a2 = *(const uint32_t*)&ap[2 * q + 8];
                uint32_t a3 = *(const uint32_t*)&ap[8 * X2 + 2 * q + 8];
#pragma unroll
                for (int nt = 0; nt < NT; nt++)
                    mma_bf16(acc[mt][nt], a0, a1, a2, a3, bb[nt].x, bb[nt].y);
            }
        }
    }

    const int y = y0 + w;
#pragma unroll
    for (int mt = 0; mt < 2; mt++) {
        int xa = x0 + mt * 16 + hr;
#pragma unroll
        for (int nt = 0; nt < NT; nt++) {
            int col = nt * 8 + 2 * q;
            float bv0 = s_bias[col], bv1 = s_bias[col + 1];
            float v0 = acc[mt][nt][0] + bv0, v1 = acc[mt][nt][1] + bv1;
            float v2 = acc[mt][nt][2] + bv0, v3 = acc[mt][nt][3] + bv1;
            if (!TRI) {
                v0 = fmaxf(v0, 0.f); v1 = fmaxf(v1, 0.f);
                v2 = fmaxf(v2, 0.f); v3 = fmaxf(v3, 0.f);
                *(uint32_t*)&outh[(((size_t)n * RESO + y) * RESO + xa) * ZD + col] = packbf(v0, v1);
                *(uint32_t*)&outh[(((size_t)n * RESO + y) * RESO + xa + 8) * ZD + col] = packbf(v2, v3);
            } else {
                int plane = col >> 5, c = col & 31;
                size_t pb = (((size_t)n * 3 + plane) * RESO * RESO);
                *(uint32_t*)&outh[(pb + (size_t)y * RESO + xa) * TD + c] = packbf(v0, v1);
                *(uint32_t*)&outh[(pb + (size_t)y * RESO + xa + 8) * TD + c] = packbf(v2, v3);
            }
        }
    }
}

// ---------------- bf16 decoder: register-resident activation pipeline ------
#define AST2 104
#define D_SA    0
#define D_B0    53248
#define D_B1    71680
#define D_B2    90112
#define D_BI0   96256
#define D_BI1   96640
#define D_BI2   97024
#define D_CW1   97152
#define D_CB1   97440
#define DEC_SMEM 97456
#define DTILES (MPTS / 32)

__global__ __launch_bounds__(256, 2) void decode_kernel(
    const float* __restrict__ coor, const float* __restrict__ spos,
    const float* __restrict__ w0, const float* __restrict__ b0,
    const float* __restrict__ w1, const float* __restrict__ b1,
    const float* __restrict__ dw, const float* __restrict__ db,
    const float* __restrict__ cw0, const float* __restrict__ cb0,
    const float* __restrict__ cw1, const float* __restrict__ cb1,
    float* __restrict__ out) {
    extern __shared__ char smraw[];
    bf16* sA = (bf16*)(smraw + D_SA);
    uint32_t* sB0 = (uint32_t*)(smraw + D_B0);
    uint32_t* sB1 = (uint32_t*)(smraw + D_B1);
    uint32_t* sB2 = (uint32_t*)(smraw + D_B2);
    float* sbi0 = (float*)(smraw + D_BI0);
    float* sbi1 = (float*)(smraw + D_BI1);
    float* sbi2 = (float*)(smraw + D_BI2);
    float* scw1 = (float*)(smraw + D_CW1);
    float* scb1 = (float*)(smraw + D_CB1);

    int tid = threadIdx.x;
    int wid = tid >> 5, lane = tid & 31;

    for (int idx = tid; idx < 96 * 96; idx += 256) {
        int k = idx / 96, n = idx % 96;
        int kb = k >> 4, rr = (k >> 3) & 1, half = k & 1;
        int lane2 = (n & 7) * 4 + ((k & 7) >> 1), nt = n >> 3;
        int hoff = ((kb * 12 + nt) * 64 + lane2 * 2 + rr) * 2 + half;
        ((bf16*)sB0)[hoff] = __float2bfloat16(w0[idx]);
        ((bf16*)sB1)[hoff] = __float2bfloat16(w1[idx]);
    }
    for (int idx = tid; idx < 96 * 32; idx += 256) {
        int k = idx / 32, n = idx % 32;
        float v = (n == 0) ? dw[k] : ((n <= 24) ? cw0[k * 24 + n - 1] : 0.f);
        int kb = k >> 4, rr = (k >> 3) & 1, half = k & 1;
        int lane2 = (n & 7) * 4 + ((k & 7) >> 1), nt = n >> 3;
        int hoff = ((kb * 4 + nt) * 64 + lane2 * 2 + rr) * 2 + half;
        ((bf16*)sB2)[hoff] = __float2bfloat16(v);
    }
    if (tid < 96) { sbi0[tid] = b0[tid]; sbi1[tid] = b1[tid]; }
    if (tid < 32) sbi2[tid] = (tid == 0) ? db[0] : ((tid <= 24) ? cb0[tid - 1] : 0.f);
    if (tid < 72) scw1[tid] = cw1[tid];
    if (tid < 3) scb1[tid] = cb1[tid];
    __syncthreads();

    const int rowbase = wid * 32;
    const int myrow = rowbase + lane;
    const int slot = lane & 7;
    const int pj = lane >> 3;
    const int g2 = lane >> 2;
    const int ch = (lane & 3) * 8;
    const int g = lane >> 2, q = lane & 3, cl = 2 * q;
    const size_t B1o = (size_t)MPTS * 4;
    const size_t B2o = B1o + (size_t)NS * MPTS * 4;
    const size_t B3o = B2o + (size_t)NS * MPTS * 4;
    float sx = spos[slot * 3 + 0], sy = spos[slot * 3 + 1], sz = spos[slot * 3 + 2];

    for (int t = blockIdx.x; t < DTILES; t += gridDim.x) {
        int m = (t << 5) + wid * 4 + pj;

        float rx = coor[((size_t)slot * MPTS + m) * 3 + 0] - sx;
        float ry = coor[((size_t)slot * MPTS + m) * 3 + 1] - sy;
        float rz = coor[((size_t)slot * MPTS + m) * 3 + 2] - sz;
        bool outsider = (fabsf(rx) > 1.f || fabsf(ry) > 1.f || fabsf(rz) > 1.f);

        float up0 = (rx + 1.f) * 64.f - 0.5f, vp0 = (ry + 1.f) * 64.f - 0.5f;
        float up1 = up0,                      vp1 = (rz + 1.f) * 64.f - 0.5f;
        float up2 = vp1,                      vp2 = up0;

        // cooperative coalesced gather (round-12, known-good)
#pragma unroll
        for (int p = 0; p < 3; p++) {
            float uo = (p == 0) ? up0 : (p == 1) ? up1 : up2;
            float vo = (p == 0) ? vp0 : (p == 1) ? vp1 : vp2;
#pragma unroll
            for (int it = 0; it < 4; it++) {
                int r = it * 8 + g2;
                float u = __shfl_sync(0xffffffffu, uo, r);
                float v = __shfl_sync(0xffffffffu, vo, r);
                float fx = floorf(u), fy = floorf(v);
                float wx = u - fx, wy = v - fy;
                int ix0 = (int)fx, iy0 = (int)fy;
                float wts[4] = {(1 - wx) * (1 - wy), wx * (1 - wy), (1 - wx) * wy, wx * wy};
                int xs[4] = {ix0, ix0 + 1, ix0, ix0 + 1};
                int ys[4] = {iy0, iy0, iy0 + 1, iy0 + 1};
                int rslot = r & 7;
                size_t pb = ((size_t)rslot * 3 + p) * RESO * RESO;
                bf162 acc4[4];
#pragma unroll
                for (int k = 0; k < 4; k++) acc4[k] = __float2bfloat162_rn(0.f);
#pragma unroll
                for (int tt = 0; tt < 4; tt++) {
                    if (xs[tt] >= 0 && xs[tt] < RESO && ys[tt] >= 0 && ys[tt] < RESO) {
                        uint4 qv = __ldg((const uint4*)&g_tri_h[(pb + (size_t)ys[tt] * RESO + xs[tt]) * TD + ch]);
                        bf162 w2 = __float2bfloat162_rn(wts[tt]);
                        acc4[0] = __hfma2(*(bf162*)&qv.x, w2, acc4[0]);
                        acc4[1] = __hfma2(*(bf162*)&qv.y, w2, acc4[1]);
                        acc4[2] = __hfma2(*(bf162*)&qv.z, w2, acc4[2]);
                        acc4[3] = __hfma2(*(bf162*)&qv.w, w2, acc4[3]);
                    }
                }
                uint4 o;
                o.x = *(uint32_t*)&acc4[0];
                o.y = *(uint32_t*)&acc4[1];
                o.z = *(uint32_t*)&acc4[2];
                o.w = *(uint32_t*)&acc4[3];
                *(uint4*)&sA[(rowbase + r) * AST2 + p * 32 + ch] = o;
            }
        }
        __syncwarp();

        // ---- layer0: smem A -> register-packed U (two N-halves) ----
        uint32_t U0[2][12], U1[2][12];
#pragma unroll
        for (int h = 0; h < 2; h++) {
            float acc[2][6][4];
#pragma unroll
            for (int j = 0; j < 6; j++) {
                float bv0 = sbi0[(h * 6 + j) * 8 + cl], bv1 = sbi0[(h * 6 + j) * 8 + cl + 1];
#pragma unroll
                for (int mt = 0; mt < 2; mt++) {
                    acc[mt][j][0] = bv0; acc[mt][j][1] = bv1;
                    acc[mt][j][2] = bv0; acc[mt][j][3] = bv1;
                }
            }
#pragma unroll
            for (int kb = 0; kb < 6; kb++) {
                uint2 bb[6];
#pragma unroll
                for (int j = 0; j < 6; j++)
                    bb[j] = *(const uint2*)&sB0[(kb * 12 + h * 6 + j) * 64 + lane * 2];
#pragma unroll
                for (int mt = 0; mt < 2; mt++) {
                    const bf16* ap = sA + (rowbase + mt * 16 + g) * AST2 + kb * 16;
                    uint32_t a0 = *(const uint32_t*)&ap[2 * q];
                    uint32_t a1 = *(const uint32_t*)&ap[8 * AST2 + 2 * q];
                    uint32_t a2 = *(const uint32_t*)&ap[2 * q + 8];
                    uint32_t a3 = *(const uint32_t*)&ap[8 * AST2 + 2 * q + 8];
#pragma unroll
                    for (int j = 0; j < 6; j++)
                        mma_bf16(acc[mt][j], a0, a1, a2, a3, bb[j].x, bb[j].y);
                }
            }
#pragma unroll
            for (int mt = 0; mt < 2; mt++)
#pragma unroll
                for (int j = 0; j < 6; j++) {
                    U0[mt][h * 6 + j] = packbf(fmaxf(acc[mt][j][0], 0.f), fmaxf(acc[mt][j][1], 0.f));
                    U1[mt][h * 6 + j] = packbf(fmaxf(acc[mt][j][2], 0.f), fmaxf(acc[mt][j][3], 0.f));
                }
        }

        // ---- layer1: register A -> register-packed V (two N-halves) ----
        uint32_t V0[2][12], V1[2][12];
#pragma unroll
        for (int h = 0; h < 2; h++) {
            float acc[2][6][4];
#pragma unroll
            for (int j = 0; j < 6; j++) {
                float bv0 = sbi1[(h * 6 + j) * 8 + cl], bv1 = sbi1[(h * 6 + j) * 8 + cl + 1];
#pragma unroll
                for (int mt = 0; mt < 2; mt++) {
                    acc[mt][j][0] = bv0; acc[mt][j][1] = bv1;
                    acc[mt][j][2] = bv0; acc[mt][j][3] = bv1;
                }
            }
#pragma unroll
            for (int kb = 0; kb < 6; kb++) {
                uint2 bb[6];
#pragma unroll
                for (int j = 0; j < 6; j++)
                    bb[j] = *(const uint2*)&sB1[(kb * 12 + h * 6 + j) * 64 + lane * 2];
#pragma unroll
                for (int mt = 0; mt < 2; mt++) {
                    uint32_t a0 = U0[mt][2 * kb], a1 = U1[mt][2 * kb];
                    uint32_t a2 = U0[mt][2 * kb + 1], a3 = U1[mt][2 * kb + 1];
#pragma unroll
                    for (int j = 0; j < 6; j++)
                        mma_bf16(acc[mt][j], a0, a1, a2, a3, bb[j].x, bb[j].y);
                }
            }
#pragma unroll
            for (int mt = 0; mt < 2; mt++)
#pragma unroll
                for (int j = 0; j < 6; j++) {
                    V0[mt][h * 6 + j] = packbf(fmaxf(acc[mt][j][0], 0.f), fmaxf(acc[mt][j][1], 0.f));
                    V1[mt][h * 6 + j] = packbf(fmaxf(acc[mt][j][2], 0.f), fmaxf(acc[mt][j][3], 0.f));
                }
        }

        // ---- layer2: register A, NT=4, write to sA for epilogue ----
        {
            float acc[2][4][4];
#pragma unroll
            for (int j = 0; j < 4; j++) {
                float bv0 = sbi2[j * 8 + cl], bv1 = sbi2[j * 8 + cl + 1];
#pragma unroll
                for (int mt = 0; mt < 2; mt++) {
                    acc[mt][j][0] = bv0; acc[mt][j][1] = bv1;
                    acc[mt][j][2] = bv0; acc[mt][j][3] = bv1;
                }
            }
#pragma unroll
            for (int kb = 0; kb < 6; kb++) {
                uint2 bb[4];
#pragma unroll
                for (int j = 0; j < 4; j++)
                    bb[j] = *(const uint2*)&sB2[(kb * 4 + j) * 64 + lane * 2];
#pragma unroll
                for (int mt = 0; mt < 2; mt++) {
                    uint32_t a0 = V0[mt][2 * kb], a1 = V1[mt][2 * kb];
                    uint32_t a2 = V0[mt][2 * kb + 1], a3 = V1[mt][2 * kb + 1];
#pragma unroll
                    for (int j = 0; j < 4; j++)
                        mma_bf16(acc[mt][j], a0, a1, a2, a3, bb[j].x, bb[j].y);
                }
            }
#pragma unroll
            for (int mt = 0; mt < 2; mt++) {
                int r0 = rowbase + mt * 16 + g;
#pragma unroll
                for (int j = 0; j < 4; j++) {
                    int col = j * 8 + cl;
                    *(uint32_t*)&sA[r0 * AST2 + col] = packbf(acc[mt][j][0], acc[mt][j][1]);
                    *(uint32_t*)&sA[(r0 + 8) * AST2 + col] = packbf(acc[mt][j][2], acc[mt][j][3]);
                }
            }
        }
        __syncwarp();

        // ---- epilogue: own row -> rgb + mask ----
        float4 um;
        {
            const bf16* vh = &sA[myrow * AST2];
            float vv[26];
#pragma unroll
            for (int i = 0; i < 13; i++) {
                float2 f2 = __bfloat1622float2(*(const bf162*)&vh[2 * i]);
                vv[2 * i] = f2.x;
                vv[2 * i + 1] = f2.y;
            }
            float dens = vv[0];
            float c0 = scb1[0], c1 = scb1[1], c2 = scb1[2];
#pragma unroll
            for (int j = 0; j < 24; j++) {
                float h = fmaxf(vv[1 + j], 0.f);
                c0 += h * scw1[j * 3 + 0];
                c1 += h * scw1[j * 3 + 1];
                c2 += h * scw1[j * 3 + 2];
            }
            float rawmask = outsider ? 0.f : fmaxf(dens, 0.f);
            um = make_float4((tanhf(c0) + 1.f) * 0.5f, (tanhf(c1) + 1.f) * 0.5f,
                             (tanhf(c2) + 1.f) * 0.5f, rawmask);
        }

        float denom = um.w;
        denom += __shfl_xor_sync(0xffffffffu, denom, 1);
        denom += __shfl_xor_sync(0xffffffffu, denom, 2);
        denom += __shfl_xor_sync(0xffffffffu, denom, 4);
        denom += 1e-8f;
        float mk = um.w / denom;
        float4 md = make_float4(um.x * mk, um.y * mk, um.z * mk, um.w * mk);

        size_t po = (size_t)slot * MPTS + m;
        *(float4*)&out[B2o + po * 4] = um;
        *(float4*)&out[B1o + po * 4] = md;
        out[B3o + po] = mk;

        float r0 = md.x, r1 = md.y, r2 = md.z, r3 = md.w;
#pragma unroll
        for (int d = 1; d <= 4; d <<= 1) {
            r0 += __shfl_xor_sync(0xffffffffu, r0, d);
            r1 += __shfl_xor_sync(0xffffffffu, r1, d);
            r2 += __shfl_xor_sync(0xffffffffu, r2, d);
            r3 += __shfl_xor_sync(0xffffffffu, r3, d);
        }
        if (slot == 0)
            *(float4*)&out[(size_t)m * 4] = make_float4(r0, r1, r2, r3);
        __syncwarp();
    }
}

// ---------------- launch ----------------------------------------------------
extern "C" void kernel_launch(void* const* d_in, const int* in_sizes, int n_in,
                              void* d_out, int out_size) {
    const float* coor = (const float*)d_in[0];
    const float* zs   = (const float*)d_in[1];
    const float* sp   = (const float*)d_in[2];
    const float* pos_w = (const float*)d_in[3];
    const float* pos_b = (const float*)d_in[4];
    const float* pe_w  = (const float*)d_in[5];
    const float* pe_b  = (const float*)d_in[6];
    const float* c1w = (const float*)d_in[7];
    const float* c1b = (const float*)d_in[8];
    const float* c2w = (const float*)d_in[9];
    const float* c2b = (const float*)d_in[10];
    const float* c3w = (const float*)d_in[11];
    const float* c3b = (const float*)d_in[12];
    const float* dw0 = (const float*)d_in[13];
    const float* db0 = (const float*)d_in[14];
    const float* dw1 = (const float*)d_in[15];
    const float* db1 = (const float*)d_in[16];
    const float* dnw = (const float*)d_in[17];
    const float* dnb = (const float*)d_in[18];
    const float* cw0 = (const float*)d_in[19];
    const float* cb0 = (const float*)d_in[20];
    const float* cw1 = (const float*)d_in[21];
    const float* cb1 = (const float*)d_in[22];
    float* out = (float*)d_out;

    bf16 *fmap, *tri, *wf2, *wf3;
    cudaGetSymbolAddress((void**)&fmap, g_fmap_h);
    cudaGetSymbolAddress((void**)&tri, g_tri_h);
    cudaGetSymbolAddress((void**)&wf2, g_wf2h);
    cudaGetSymbolAddress((void**)&wf3, g_wf3h);

    prep_all_kernel<<<161, 576>>>(zs, sp, pos_w, pos_b, pe_w, pe_b,
                                  c1w, c1b, c2w, c3w);

    const int smem2 = SIN_H * 2 + 64 * 4;
    const int smem3 = SIN_H * 2 + 96 * 4;
    cudaFuncSetAttribute((const void*)conv_tc_kernel<64, true, false>,
                         cudaFuncAttributeMaxDynamicSharedMemorySize, smem2);
    cudaFuncSetAttribute((const void*)conv_tc_kernel<96, false, true>,
                         cudaFuncAttributeMaxDynamicSharedMemorySize, smem3);

    dim3 cg(4, 32, NS);
    conv_tc_kernel<64, true, false><<<cg, 128, smem2>>>((const uint2*)wf2, c2b, c1b, fmap);
    conv_tc_kernel<96, false, true><<<cg, 128, smem3>>>((const uint2*)wf3, c3b, c1b, tri);

    cudaFuncSetAttribute(decode_kernel, cudaFuncAttributeMaxDynamicSharedMemorySize, DEC_SMEM);
    decode_kernel<<<296, 256, DEC_SMEM>>>(
        coor, sp, dw0, db0, dw1, db1, dnw, dnb, cw0, cb0, cw1, cb1, out);
}